// round 3
// baseline (speedup 1.0000x reference)
#include <cuda_runtime.h>
#include <cuda_bf16.h>
#include <math.h>

// Problem constants
#define E_   2048
#define H_   16
#define D_   128
#define B_   4
#define T_   1024
#define TP_  3072
#define S_   (TP_ + T_)      // 4096
#define NTOK (B_ * T_)       // 4096
#define QSCALE 0.08838834764831845f   // 1/sqrt(128)

// Scratch (device globals -- no allocations allowed)
__device__ float g_q[NTOK * E_];
__device__ float g_attn[NTOK * E_];

// ---------------------------------------------------------------------------
// Helpers
// ---------------------------------------------------------------------------
__device__ __forceinline__ unsigned f2tf32(float f) {
    unsigned u;
    asm("cvt.rna.tf32.f32 %0, %1;" : "=r"(u) : "f"(f));
    return u;
}

__device__ __forceinline__ void mma_tf32(float c[4],
    unsigned a0, unsigned a1, unsigned a2, unsigned a3,
    unsigned b0, unsigned b1)
{
    asm volatile(
        "mma.sync.aligned.m16n8k8.row.col.f32.tf32.tf32.f32 "
        "{%0,%1,%2,%3}, {%4,%5,%6,%7}, {%8,%9}, {%0,%1,%2,%3};"
        : "+f"(c[0]), "+f"(c[1]), "+f"(c[2]), "+f"(c[3])
        : "r"(a0), "r"(a1), "r"(a2), "r"(a3), "r"(b0), "r"(b1));
}

__device__ __forceinline__ unsigned s2u(const void* p) {
    return (unsigned)__cvta_generic_to_shared(p);
}

#define CP16(dst_u32, src_ptr) \
    asm volatile("cp.async.cg.shared.global [%0], [%1], 16;" :: "r"(dst_u32), "l"(src_ptr))
#define CP_COMMIT() asm volatile("cp.async.commit_group;")
#define CP_WAIT0()  asm volatile("cp.async.wait_group 0;")
#define CP_WAIT1()  asm volatile("cp.async.wait_group 1;")

// ---------------------------------------------------------------------------
// Fused QKV GEMM: z in {0,1,2} selects Wq/Wk/Wv.
// C[n,m] = A[n,:] . W[m,:] + bias[m]
// z=0 -> g_q (pre-scaled by 1/sqrt(D));  z=1 -> K cache;  z=2 -> V cache.
// Block 128x128x32, 2-stage cp.async pipeline, raw f32 in smem,
// cvt.rna.tf32 at fragment load. Pitch 36 (conflict-free).
// ---------------------------------------------------------------------------
#define GP 36

__global__ __launch_bounds__(256, 2) void qkv_gemm(
    const float* __restrict__ A,
    const float* __restrict__ Wq, const float* __restrict__ bq,
    const float* __restrict__ Wk, const float* __restrict__ bk,
    const float* __restrict__ Wv, const float* __restrict__ bv,
    float* __restrict__ q_out, float* __restrict__ kc, float* __restrict__ vc)
{
    extern __shared__ float sm[];
    float* sA[2] = { sm,                sm + 128 * GP     };
    float* sB[2] = { sm + 2 * 128 * GP, sm + 3 * 128 * GP };

    const int z = blockIdx.z;
    const float* W    = (z == 0) ? Wq : (z == 1) ? Wk : Wv;
    const float* bias = (z == 0) ? bq : (z == 1) ? bk : bv;

    const int tid  = threadIdx.x;
    const int lane = tid & 31, wid = tid >> 5;
    const int wm = wid >> 1, wn = wid & 1;
    const int g = lane >> 2, t = lane & 3;
    const int brow = blockIdx.y * 128, bcol = blockIdx.x * 128;

    const int lr = tid >> 3;            // 0..31 row within slab of 32
    const int lc = (tid & 7) * 4;       // 0,4,..,28

    float acc[2][8][4];
#pragma unroll
    for (int mi = 0; mi < 2; mi++)
#pragma unroll
        for (int nj = 0; nj < 8; nj++)
#pragma unroll
            for (int q = 0; q < 4; q++) acc[mi][nj][q] = 0.f;

    // prologue: stage 0
#pragma unroll
    for (int l = 0; l < 4; l++) {
        int r = lr + l * 32;
        CP16(s2u(&sA[0][r * GP + lc]), &A[(size_t)(brow + r) * E_ + lc]);
        CP16(s2u(&sB[0][r * GP + lc]), &W[(size_t)(bcol + r) * E_ + lc]);
    }
    CP_COMMIT();

    for (int kt = 0; kt < E_ / 32; kt++) {
        const int cur = kt & 1;
        CP_WAIT0();
        __syncthreads();
        if (kt + 1 < E_ / 32) {
            const int k0 = (kt + 1) * 32;
#pragma unroll
            for (int l = 0; l < 4; l++) {
                int r = lr + l * 32;
                CP16(s2u(&sA[cur ^ 1][r * GP + lc]), &A[(size_t)(brow + r) * E_ + k0 + lc]);
                CP16(s2u(&sB[cur ^ 1][r * GP + lc]), &W[(size_t)(bcol + r) * E_ + k0 + lc]);
            }
            CP_COMMIT();
        }

        const float* cA = sA[cur];
        const float* cB = sB[cur];
#pragma unroll
        for (int ks = 0; ks < 4; ks++) {
            unsigned a[2][4];
#pragma unroll
            for (int mi = 0; mi < 2; mi++) {
                int r = wm * 32 + mi * 16 + g;
                a[mi][0] = f2tf32(cA[r * GP + ks * 8 + t]);
                a[mi][1] = f2tf32(cA[(r + 8) * GP + ks * 8 + t]);
                a[mi][2] = f2tf32(cA[r * GP + ks * 8 + t + 4]);
                a[mi][3] = f2tf32(cA[(r + 8) * GP + ks * 8 + t + 4]);
            }
#pragma unroll
            for (int nj = 0; nj < 8; nj++) {
                int n = wn * 64 + nj * 8 + g;
                unsigned b0 = f2tf32(cB[n * GP + ks * 8 + t]);
                unsigned b1 = f2tf32(cB[n * GP + ks * 8 + t + 4]);
                mma_tf32(acc[0][nj], a[0][0], a[0][1], a[0][2], a[0][3], b0, b1);
                mma_tf32(acc[1][nj], a[1][0], a[1][1], a[1][2], a[1][3], b0, b1);
            }
        }
    }
    __syncthreads();

    // epilogue
#pragma unroll
    for (int mi = 0; mi < 2; mi++) {
#pragma unroll
        for (int nj = 0; nj < 8; nj++) {
            int row = brow + wm * 32 + mi * 16 + g;
            int col = bcol + wn * 64 + nj * 8 + t * 2;
            float b0 = bias[col], b1 = bias[col + 1];
            float v00 = acc[mi][nj][0] + b0, v01 = acc[mi][nj][1] + b1;
            float v10 = acc[mi][nj][2] + b0, v11 = acc[mi][nj][3] + b1;
            if (z == 0) {
                float2 p0 = { v00 * QSCALE, v01 * QSCALE };
                float2 p1 = { v10 * QSCALE, v11 * QSCALE };
                *(float2*)&q_out[(size_t)row * E_ + col]       = p0;
                *(float2*)&q_out[(size_t)(row + 8) * E_ + col] = p1;
            } else {
                float* dst = (z == 1) ? kc : vc;
                // row = b*T + t ; col = h*D + d -> cache[(b*H+h)*S + TP + t, d]
                int b_i = row >> 10, t_i = row & 1023;
                int h_i = col >> 7,  d_i = col & 127;
                size_t base = ((size_t)(b_i * H_ + h_i) * S_ + TP_ + t_i) * D_ + d_i;
                float2 p0 = { v00, v01 };
                float2 p1 = { v10, v11 };
                *(float2*)&dst[base]              = p0;
                *(float2*)&dst[base + 8ull * D_]  = p1;
            }
        }
    }
}

// ---------------------------------------------------------------------------
// Plain GEMM for output projection (same pipeline, plain epilogue)
// ---------------------------------------------------------------------------
__global__ __launch_bounds__(256, 2) void gemm_plain(
    const float* __restrict__ A, const float* __restrict__ W,
    const float* __restrict__ bias, float* __restrict__ C)
{
    extern __shared__ float sm[];
    float* sA[2] = { sm,                sm + 128 * GP     };
    float* sB[2] = { sm + 2 * 128 * GP, sm + 3 * 128 * GP };

    const int tid  = threadIdx.x;
    const int lane = tid & 31, wid = tid >> 5;
    const int wm = wid >> 1, wn = wid & 1;
    const int g = lane >> 2, t = lane & 3;
    const int brow = blockIdx.y * 128, bcol = blockIdx.x * 128;
    const int lr = tid >> 3, lc = (tid & 7) * 4;

    float acc[2][8][4];
#pragma unroll
    for (int mi = 0; mi < 2; mi++)
#pragma unroll
        for (int nj = 0; nj < 8; nj++)
#pragma unroll
            for (int q = 0; q < 4; q++) acc[mi][nj][q] = 0.f;

#pragma unroll
    for (int l = 0; l < 4; l++) {
        int r = lr + l * 32;
        CP16(s2u(&sA[0][r * GP + lc]), &A[(size_t)(brow + r) * E_ + lc]);
        CP16(s2u(&sB[0][r * GP + lc]), &W[(size_t)(bcol + r) * E_ + lc]);
    }
    CP_COMMIT();

    for (int kt = 0; kt < E_ / 32; kt++) {
        const int cur = kt & 1;
        CP_WAIT0();
        __syncthreads();
        if (kt + 1 < E_ / 32) {
            const int k0 = (kt + 1) * 32;
#pragma unroll
            for (int l = 0; l < 4; l++) {
                int r = lr + l * 32;
                CP16(s2u(&sA[cur ^ 1][r * GP + lc]), &A[(size_t)(brow + r) * E_ + k0 + lc]);
                CP16(s2u(&sB[cur ^ 1][r * GP + lc]), &W[(size_t)(bcol + r) * E_ + k0 + lc]);
            }
            CP_COMMIT();
        }

        const float* cA = sA[cur];
        const float* cB = sB[cur];
#pragma unroll
        for (int ks = 0; ks < 4; ks++) {
            unsigned a[2][4];
#pragma unroll
            for (int mi = 0; mi < 2; mi++) {
                int r = wm * 32 + mi * 16 + g;
                a[mi][0] = f2tf32(cA[r * GP + ks * 8 + t]);
                a[mi][1] = f2tf32(cA[(r + 8) * GP + ks * 8 + t]);
                a[mi][2] = f2tf32(cA[r * GP + ks * 8 + t + 4]);
                a[mi][3] = f2tf32(cA[(r + 8) * GP + ks * 8 + t + 4]);
            }
#pragma unroll
            for (int nj = 0; nj < 8; nj++) {
                int n = wn * 64 + nj * 8 + g;
                unsigned b0 = f2tf32(cB[n * GP + ks * 8 + t]);
                unsigned b1 = f2tf32(cB[n * GP + ks * 8 + t + 4]);
                mma_tf32(acc[0][nj], a[0][0], a[0][1], a[0][2], a[0][3], b0, b1);
                mma_tf32(acc[1][nj], a[1][0], a[1][1], a[1][2], a[1][3], b0, b1);
            }
        }
    }
    __syncthreads();

#pragma unroll
    for (int mi = 0; mi < 2; mi++) {
#pragma unroll
        for (int nj = 0; nj < 8; nj++) {
            int row = brow + wm * 32 + mi * 16 + g;
            int col = bcol + wn * 64 + nj * 8 + t * 2;
            float b0 = bias[col], b1 = bias[col + 1];
            float2 v0 = { acc[mi][nj][0] + b0, acc[mi][nj][1] + b1 };
            float2 v1 = { acc[mi][nj][2] + b0, acc[mi][nj][3] + b1 };
            *(float2*)&C[(size_t)row * E_ + col]       = v0;
            *(float2*)&C[(size_t)(row + 8) * E_ + col] = v1;
        }
    }
}

// ---------------------------------------------------------------------------
// Copy past_k/past_v [B,H,TP,D] into cache positions [0, TP)
// ---------------------------------------------------------------------------
__global__ void copy_past(const float* __restrict__ pk,
                          const float* __restrict__ pv,
                          float* __restrict__ kc, float* __restrict__ vc)
{
    int idx = blockIdx.x * blockDim.x + threadIdx.x;   // float4 index
    const int total4 = B_ * H_ * TP_ * D_ / 4;
    if (idx >= total4) return;
    int bh  = idx / (TP_ * D_ / 4);
    int off = (idx % (TP_ * D_ / 4)) * 4;
    size_t dst = (size_t)bh * S_ * D_ + off;
    *(float4*)&kc[dst] = *(const float4*)&pk[(size_t)idx * 4];
    *(float4*)&vc[dst] = *(const float4*)&pv[(size_t)idx * 4];
}

// ---------------------------------------------------------------------------
// Tensor-core flash attention, cp.async pipelined.
// CTA = (qtile 128, h, b). 256 thr, 8 warps; warp w owns rows [w*16, w*16+16).
// K double-buffered (next chunk prefetched), V prefetched during QK.
// smem: Q(tf32) 128x132, K raw f32 2x64x136, V raw f32 64x136, P(tf32) 128x68.
// ---------------------------------------------------------------------------
#define QP  132
#define KVP 136
#define PP  68

__global__ __launch_bounds__(256) void attn_tc(
    const float* __restrict__ kcache, const float* __restrict__ vcache)
{
    extern __shared__ unsigned smu[];
    unsigned* sQ = smu;                          // 128 x 132 (tf32)
    float*    sK = (float*)(sQ + 128 * QP);      // 2 x 64 x 136 (raw f32)
    float*    sV = sK + 2 * 64 * KVP;            // 64 x 136 (raw f32)
    unsigned* sP = (unsigned*)(sV + 64 * KVP);   // 128 x 68 (tf32)

    const int qt = blockIdx.x, h = blockIdx.y, b = blockIdx.z;
    const int tid = threadIdx.x, lane = tid & 31, w = tid >> 5;
    const int g = lane >> 2, t = lane & 3;

    const float* kb = kcache + (size_t)(b * H_ + h) * S_ * D_;
    const float* vb = vcache + (size_t)(b * H_ + h) * S_ * D_;

    const int lr = tid >> 5;              // 0..7
    const int lc = (tid & 31) * 4;        // 0..124

    // prologue: prefetch K chunk 0
#pragma unroll
    for (int l = 0; l < 8; l++) {
        int r = lr + l * 8;
        CP16(s2u(&sK[r * KVP + lc]), &kb[(size_t)r * D_ + lc]);
    }
    CP_COMMIT();

    // stage Q tile (already scaled in projection), tf32
#pragma unroll
    for (int l = 0; l < 16; l++) {
        int i = tid + l * 256;
        int r = i >> 5, c = (i & 31) * 4;
        float4 qv = *(const float4*)&g_q[(size_t)(b * T_ + qt * 128 + r) * E_ + h * D_ + c];
        sQ[r * QP + c + 0] = f2tf32(qv.x);
        sQ[r * QP + c + 1] = f2tf32(qv.y);
        sQ[r * QP + c + 2] = f2tf32(qv.z);
        sQ[r * QP + c + 3] = f2tf32(qv.w);
    }

    float m0 = -1e30f, m1 = -1e30f, l0 = 0.f, l1 = 0.f;
    float acc_o[16][4];
#pragma unroll
    for (int nj = 0; nj < 16; nj++)
#pragma unroll
        for (int q = 0; q < 4; q++) acc_o[nj][q] = 0.f;

    for (int ci = 0; ci < S_ / 64; ci++) {
        const int cur = ci & 1;
        const float* cK = sK + cur * 64 * KVP;

        CP_WAIT0();
        __syncthreads();     // K_ci visible to all; prior chunk fully consumed

        // prefetch V_ci, then K_{ci+1}
        {
            const size_t vbase = (size_t)(ci * 64) * D_;
#pragma unroll
            for (int l = 0; l < 8; l++) {
                int r = lr + l * 8;
                CP16(s2u(&sV[r * KVP + lc]), &vb[vbase + (size_t)r * D_ + lc]);
            }
            CP_COMMIT();
        }
        if (ci + 1 < S_ / 64) {
            const size_t kbase = (size_t)((ci + 1) * 64) * D_;
            float* nK = sK + (cur ^ 1) * 64 * KVP;
#pragma unroll
            for (int l = 0; l < 8; l++) {
                int r = lr + l * 8;
                CP16(s2u(&nK[r * KVP + lc]), &kb[kbase + (size_t)r * D_ + lc]);
            }
            CP_COMMIT();
        }

        // S = Q K^T
        float accs[8][4];
#pragma unroll
        for (int nj = 0; nj < 8; nj++)
#pragma unroll
            for (int q = 0; q < 4; q++) accs[nj][q] = 0.f;

#pragma unroll
        for (int ks = 0; ks < 16; ks++) {
            int r = w * 16 + g;
            unsigned a0 = sQ[r * QP + ks * 8 + t];
            unsigned a1 = sQ[(r + 8) * QP + ks * 8 + t];
            unsigned a2 = sQ[r * QP + ks * 8 + t + 4];
            unsigned a3 = sQ[(r + 8) * QP + ks * 8 + t + 4];
#pragma unroll
            for (int nj = 0; nj < 8; nj++) {
                unsigned b0 = f2tf32(cK[(nj * 8 + g) * KVP + ks * 8 + t]);
                unsigned b1 = f2tf32(cK[(nj * 8 + g) * KVP + ks * 8 + t + 4]);
                mma_tf32(accs[nj], a0, a1, a2, a3, b0, b1);
            }
        }

        // online softmax
        float rm0 = -1e30f, rm1 = -1e30f;
#pragma unroll
        for (int nj = 0; nj < 8; nj++) {
            rm0 = fmaxf(rm0, fmaxf(accs[nj][0], accs[nj][1]));
            rm1 = fmaxf(rm1, fmaxf(accs[nj][2], accs[nj][3]));
        }
        rm0 = fmaxf(rm0, __shfl_xor_sync(0xffffffffu, rm0, 1));
        rm0 = fmaxf(rm0, __shfl_xor_sync(0xffffffffu, rm0, 2));
        rm1 = fmaxf(rm1, __shfl_xor_sync(0xffffffffu, rm1, 1));
        rm1 = fmaxf(rm1, __shfl_xor_sync(0xffffffffu, rm1, 2));

        float nm0 = fmaxf(m0, rm0), nm1 = fmaxf(m1, rm1);
        float al0 = __expf(m0 - nm0), al1 = __expf(m1 - nm1);
        m0 = nm0; m1 = nm1;

        float sum0 = 0.f, sum1 = 0.f;
        int r0 = w * 16 + g;
#pragma unroll
        for (int nj = 0; nj < 8; nj++) {
            float p0 = __expf(accs[nj][0] - nm0);
            float p1 = __expf(accs[nj][1] - nm0);
            float p2 = __expf(accs[nj][2] - nm1);
            float p3 = __expf(accs[nj][3] - nm1);
            sum0 += p0 + p1;
            sum1 += p2 + p3;
            int c = nj * 8 + t * 2;
            uint2 u0 = { f2tf32(p0), f2tf32(p1) };
            uint2 u1 = { f2tf32(p2), f2tf32(p3) };
            *(uint2*)&sP[r0 * PP + c]       = u0;
            *(uint2*)&sP[(r0 + 8) * PP + c] = u1;
        }
        sum0 += __shfl_xor_sync(0xffffffffu, sum0, 1);
        sum0 += __shfl_xor_sync(0xffffffffu, sum0, 2);
        sum1 += __shfl_xor_sync(0xffffffffu, sum1, 1);
        sum1 += __shfl_xor_sync(0xffffffffu, sum1, 2);
        l0 = l0 * al0 + sum0;
        l1 = l1 * al1 + sum1;

#pragma unroll
        for (int nj = 0; nj < 16; nj++) {
            acc_o[nj][0] *= al0; acc_o[nj][1] *= al0;
            acc_o[nj][2] *= al1; acc_o[nj][3] *= al1;
        }

        // wait for V (leave K_{ci+1} group pending)
        if (ci + 1 < S_ / 64) { CP_WAIT1(); } else { CP_WAIT0(); }
        __syncthreads();

        // O += P V
#pragma unroll
        for (int ks = 0; ks < 8; ks++) {
            unsigned a0 = sP[(w * 16 + g) * PP + ks * 8 + t];
            unsigned a1 = sP[(w * 16 + g + 8) * PP + ks * 8 + t];
            unsigned a2 = sP[(w * 16 + g) * PP + ks * 8 + t + 4];
            unsigned a3 = sP[(w * 16 + g + 8) * PP + ks * 8 + t + 4];
#pragma unroll
            for (int nj = 0; nj < 16; nj++) {
                unsigned b0 = f2tf32(sV[(ks * 8 + t) * KVP + nj * 8 + g]);
                unsigned b1 = f2tf32(sV[(ks * 8 + t + 4) * KVP + nj * 8 + g]);
                mma_tf32(acc_o[nj], a0, a1, a2, a3, b0, b1);
            }
        }
    }

    // epilogue: normalize, write row-major [NTOK, E]
    float inv0 = 1.f / l0, inv1 = 1.f / l1;
    int row = b * T_ + qt * 128 + w * 16 + g;
#pragma unroll
    for (int nj = 0; nj < 16; nj++) {
        int col = h * D_ + nj * 8 + t * 2;
        float2 v0 = { acc_o[nj][0] * inv0, acc_o[nj][1] * inv0 };
        float2 v1 = { acc_o[nj][2] * inv1, acc_o[nj][3] * inv1 };
        *(float2*)&g_attn[(size_t)row * E_ + col]       = v0;
        *(float2*)&g_attn[(size_t)(row + 8) * E_ + col] = v1;
    }
}

// ---------------------------------------------------------------------------
extern "C" void kernel_launch(void* const* d_in, const int* in_sizes, int n_in,
                              void* d_out, int out_size)
{
    const float* x      = (const float*)d_in[0];
    const float* past_k = (const float*)d_in[1];
    const float* past_v = (const float*)d_in[2];
    const float* Wq     = (const float*)d_in[3];
    const float* bq     = (const float*)d_in[4];
    const float* Wk     = (const float*)d_in[5];
    const float* bk     = (const float*)d_in[6];
    const float* Wv     = (const float*)d_in[7];
    const float* bv     = (const float*)d_in[8];
    const float* Wo     = (const float*)d_in[9];
    const float* bo     = (const float*)d_in[10];

    float* out = (float*)d_out;                       // [B,T,E]
    float* kc  = out + (size_t)NTOK * E_;             // [B,H,S,D]
    float* vc  = kc + (size_t)B_ * H_ * S_ * D_;      // [B,H,S,D]

    void *pq, *pattn;
    cudaGetSymbolAddress(&pq, g_q);
    cudaGetSymbolAddress(&pattn, g_attn);

    const size_t gemm_smem = (size_t)4 * 128 * GP * sizeof(float);   // ~73.7 KB
    cudaFuncSetAttribute(qkv_gemm,  cudaFuncAttributeMaxDynamicSharedMemorySize, (int)gemm_smem);
    cudaFuncSetAttribute(gemm_plain, cudaFuncAttributeMaxDynamicSharedMemorySize, (int)gemm_smem);

    // past copy first (independent of everything)
    {
        int total4 = B_ * H_ * TP_ * D_ / 4;
        copy_past<<<(total4 + 255) / 256, 256>>>(past_k, past_v, kc, vc);
    }

    // fused QKV projections (K/V scattered directly into cache)
    dim3 gq(E_ / 128, NTOK / 128, 3);
    qkv_gemm<<<gq, 256, gemm_smem>>>(x, Wq, bq, Wk, bk, Wv, bv,
                                     (float*)pq, kc, vc);

    // attention
    size_t attn_smem = (size_t)(128 * QP + 3 * 64 * KVP + 128 * PP) * 4;
    cudaFuncSetAttribute(attn_tc, cudaFuncAttributeMaxDynamicSharedMemorySize, (int)attn_smem);
    attn_tc<<<dim3(T_ / 128, H_, B_), 256, attn_smem>>>(kc, vc);

    // output projection
    dim3 gg(E_ / 128, NTOK / 128);
    gemm_plain<<<gg, 256, gemm_smem>>>((const float*)pattn, Wo, bo, out);
}

// round 4
// speedup vs baseline: 1.6511x; 1.6511x over previous
#include <cuda_runtime.h>
#include <cuda_bf16.h>
#include <math.h>

// Problem constants
#define E_   2048
#define H_   16
#define D_   128
#define B_   4
#define T_   1024
#define TP_  3072
#define S_   (TP_ + T_)      // 4096
#define NTOK (B_ * T_)       // 4096
#define CACHE_ELEMS (B_ * H_ * S_ * D_)   // 33.5M
#define QSCALE 0.08838834764831845f       // 1/sqrt(128)

// Scratch (device globals -- no allocations allowed)
__device__ float g_q[NTOK * E_];        // rounded + scaled Q
__device__ float g_attn[NTOK * E_];     // rounded attention output
__device__ float g_xt[NTOK * E_];       // rounded x
__device__ float g_wqt[E_ * E_];
__device__ float g_wkt[E_ * E_];
__device__ float g_wvt[E_ * E_];
__device__ float g_wot[E_ * E_];
__device__ float g_kt[CACHE_ELEMS];     // rounded K cache (attention input)
__device__ float g_vt[CACHE_ELEMS];     // rounded V cache

// ---------------------------------------------------------------------------
// Helpers
// ---------------------------------------------------------------------------
__device__ __forceinline__ unsigned f2tf32(float f) {
    unsigned u;
    asm("cvt.rna.tf32.f32 %0, %1;" : "=r"(u) : "f"(f));
    return u;
}

__device__ __forceinline__ void mma_tf32(float c[4],
    unsigned a0, unsigned a1, unsigned a2, unsigned a3,
    unsigned b0, unsigned b1)
{
    asm volatile(
        "mma.sync.aligned.m16n8k8.row.col.f32.tf32.tf32.f32 "
        "{%0,%1,%2,%3}, {%4,%5,%6,%7}, {%8,%9}, {%0,%1,%2,%3};"
        : "+f"(c[0]), "+f"(c[1]), "+f"(c[2]), "+f"(c[3])
        : "r"(a0), "r"(a1), "r"(a2), "r"(a3), "r"(b0), "r"(b1));
}

__device__ __forceinline__ unsigned s2u(const void* p) {
    return (unsigned)__cvta_generic_to_shared(p);
}

#define CP16(dst_u32, src_ptr) \
    asm volatile("cp.async.cg.shared.global [%0], [%1], 16;" :: "r"(dst_u32), "l"(src_ptr))
#define CP_COMMIT() asm volatile("cp.async.commit_group;")
#define CP_WAIT0()  asm volatile("cp.async.wait_group 0;")
#define CP_WAIT1()  asm volatile("cp.async.wait_group 1;")

// ---------------------------------------------------------------------------
// Pre-round a tensor to tf32-representable fp32 (bitwise tf32 operands)
// ---------------------------------------------------------------------------
__global__ void round_tf32(const float* __restrict__ src,
                           float* __restrict__ dst, int n4)
{
    int i = blockIdx.x * blockDim.x + threadIdx.x;
    if (i >= n4) return;
    float4 v = ((const float4*)src)[i];
    uint4 u = { f2tf32(v.x), f2tf32(v.y), f2tf32(v.z), f2tf32(v.w) };
    ((uint4*)dst)[i] = u;
}

// ---------------------------------------------------------------------------
// GEMM core (all operands pre-rounded tf32 bits; zero CVT in loop)
// Block 128x128x32, 2-stage cp.async pipeline, pitch 36.
// ---------------------------------------------------------------------------
#define GP 36

struct GemmAcc { float a[2][8][4]; };

__device__ __forceinline__ void gemm_core(
    const float* __restrict__ A, const float* __restrict__ W,
    unsigned* sm, int brow, int bcol, GemmAcc& acc)
{
    unsigned* sA[2] = { sm,                sm + 128 * GP     };
    unsigned* sB[2] = { sm + 2 * 128 * GP, sm + 3 * 128 * GP };

    const int tid  = threadIdx.x;
    const int lane = tid & 31, wid = tid >> 5;
    const int wm = wid >> 1, wn = wid & 1;
    const int g = lane >> 2, t = lane & 3;
    const int lr = tid >> 3, lc = (tid & 7) * 4;

#pragma unroll
    for (int mi = 0; mi < 2; mi++)
#pragma unroll
        for (int nj = 0; nj < 8; nj++)
#pragma unroll
            for (int q = 0; q < 4; q++) acc.a[mi][nj][q] = 0.f;

#pragma unroll
    for (int l = 0; l < 4; l++) {
        int r = lr + l * 32;
        CP16(s2u(&sA[0][r * GP + lc]), &A[(size_t)(brow + r) * E_ + lc]);
        CP16(s2u(&sB[0][r * GP + lc]), &W[(size_t)(bcol + r) * E_ + lc]);
    }
    CP_COMMIT();

    for (int kt = 0; kt < E_ / 32; kt++) {
        const int cur = kt & 1;
        CP_WAIT0();
        __syncthreads();
        if (kt + 1 < E_ / 32) {
            const int k0 = (kt + 1) * 32;
#pragma unroll
            for (int l = 0; l < 4; l++) {
                int r = lr + l * 32;
                CP16(s2u(&sA[cur ^ 1][r * GP + lc]), &A[(size_t)(brow + r) * E_ + k0 + lc]);
                CP16(s2u(&sB[cur ^ 1][r * GP + lc]), &W[(size_t)(bcol + r) * E_ + k0 + lc]);
            }
            CP_COMMIT();
        }

        const unsigned* cA = sA[cur];
        const unsigned* cB = sB[cur];
#pragma unroll
        for (int ks = 0; ks < 4; ks++) {
            unsigned a[2][4];
#pragma unroll
            for (int mi = 0; mi < 2; mi++) {
                int r = wm * 32 + mi * 16 + g;
                a[mi][0] = cA[r * GP + ks * 8 + t];
                a[mi][1] = cA[(r + 8) * GP + ks * 8 + t];
                a[mi][2] = cA[r * GP + ks * 8 + t + 4];
                a[mi][3] = cA[(r + 8) * GP + ks * 8 + t + 4];
            }
#pragma unroll
            for (int nj = 0; nj < 8; nj++) {
                int n = wn * 64 + nj * 8 + g;
                unsigned b0 = cB[n * GP + ks * 8 + t];
                unsigned b1 = cB[n * GP + ks * 8 + t + 4];
                mma_tf32(acc.a[0][nj], a[0][0], a[0][1], a[0][2], a[0][3], b0, b1);
                mma_tf32(acc.a[1][nj], a[1][0], a[1][1], a[1][2], a[1][3], b0, b1);
            }
        }
    }
    __syncthreads();
}

// ---------------------------------------------------------------------------
// Fused QKV GEMM: z selects Wq/Wk/Wv; K/V dual-written (full cache + rounded)
// ---------------------------------------------------------------------------
__global__ __launch_bounds__(256, 2) void qkv_gemm(
    const float* __restrict__ A,
    const float* __restrict__ bq, const float* __restrict__ bk,
    const float* __restrict__ bv,
    float* __restrict__ q_out, float* __restrict__ kc, float* __restrict__ vc,
    float* __restrict__ ktr, float* __restrict__ vtr)
{
    extern __shared__ unsigned smu[];
    const int z = blockIdx.z;
    const float* W    = (z == 0) ? g_wqt : (z == 1) ? g_wkt : g_wvt;
    const float* bias = (z == 0) ? bq    : (z == 1) ? bk    : bv;

    const int brow = blockIdx.y * 128, bcol = blockIdx.x * 128;
    GemmAcc acc;
    gemm_core(A, W, smu, brow, bcol, acc);

    const int lane = threadIdx.x & 31, wid = threadIdx.x >> 5;
    const int wm = wid >> 1, wn = wid & 1;
    const int g = lane >> 2, t = lane & 3;

#pragma unroll
    for (int mi = 0; mi < 2; mi++) {
#pragma unroll
        for (int nj = 0; nj < 8; nj++) {
            int row = brow + wm * 32 + mi * 16 + g;
            int col = bcol + wn * 64 + nj * 8 + t * 2;
            float b0 = bias[col], b1 = bias[col + 1];
            float v00 = acc.a[mi][nj][0] + b0, v01 = acc.a[mi][nj][1] + b1;
            float v10 = acc.a[mi][nj][2] + b0, v11 = acc.a[mi][nj][3] + b1;
            if (z == 0) {
                uint2 p0 = { f2tf32(v00 * QSCALE), f2tf32(v01 * QSCALE) };
                uint2 p1 = { f2tf32(v10 * QSCALE), f2tf32(v11 * QSCALE) };
                *(uint2*)&q_out[(size_t)row * E_ + col]       = p0;
                *(uint2*)&q_out[(size_t)(row + 8) * E_ + col] = p1;
            } else {
                float* dst  = (z == 1) ? kc  : vc;
                float* dstT = (z == 1) ? ktr : vtr;
                int b_i = row >> 10, t_i = row & 1023;
                int h_i = col >> 7,  d_i = col & 127;
                size_t base = ((size_t)(b_i * H_ + h_i) * S_ + TP_ + t_i) * D_ + d_i;
                float2 p0 = { v00, v01 };
                float2 p1 = { v10, v11 };
                *(float2*)&dst[base]             = p0;
                *(float2*)&dst[base + 8ull * D_] = p1;
                uint2 r0 = { f2tf32(v00), f2tf32(v01) };
                uint2 r1 = { f2tf32(v10), f2tf32(v11) };
                *(uint2*)&dstT[base]             = r0;
                *(uint2*)&dstT[base + 8ull * D_] = r1;
            }
        }
    }
}

// ---------------------------------------------------------------------------
// Output projection GEMM (operands pre-rounded)
// ---------------------------------------------------------------------------
__global__ __launch_bounds__(256, 2) void gemm_plain(
    const float* __restrict__ A, const float* __restrict__ W,
    const float* __restrict__ bias, float* __restrict__ C)
{
    extern __shared__ unsigned smu[];
    const int brow = blockIdx.y * 128, bcol = blockIdx.x * 128;
    GemmAcc acc;
    gemm_core(A, W, smu, brow, bcol, acc);

    const int lane = threadIdx.x & 31, wid = threadIdx.x >> 5;
    const int wm = wid >> 1, wn = wid & 1;
    const int g = lane >> 2, t = lane & 3;

#pragma unroll
    for (int mi = 0; mi < 2; mi++) {
#pragma unroll
        for (int nj = 0; nj < 8; nj++) {
            int row = brow + wm * 32 + mi * 16 + g;
            int col = bcol + wn * 64 + nj * 8 + t * 2;
            float b0 = bias[col], b1 = bias[col + 1];
            float2 v0 = { acc.a[mi][nj][0] + b0, acc.a[mi][nj][1] + b1 };
            float2 v1 = { acc.a[mi][nj][2] + b0, acc.a[mi][nj][3] + b1 };
            *(float2*)&C[(size_t)row * E_ + col]       = v0;
            *(float2*)&C[(size_t)(row + 8) * E_ + col] = v1;
        }
    }
}

// ---------------------------------------------------------------------------
// Copy past K/V into cache (full) + rounded shadow
// ---------------------------------------------------------------------------
__global__ void copy_past(const float* __restrict__ pk,
                          const float* __restrict__ pv,
                          float* __restrict__ kc, float* __restrict__ vc,
                          float* __restrict__ ktr, float* __restrict__ vtr)
{
    int idx = blockIdx.x * blockDim.x + threadIdx.x;   // float4 index
    const int total4 = B_ * H_ * TP_ * D_ / 4;
    if (idx >= total4) return;
    int bh  = idx / (TP_ * D_ / 4);
    int off = (idx % (TP_ * D_ / 4)) * 4;
    size_t dst = (size_t)bh * S_ * D_ + off;
    float4 kv = *(const float4*)&pk[(size_t)idx * 4];
    float4 vv = *(const float4*)&pv[(size_t)idx * 4];
    *(float4*)&kc[dst] = kv;
    *(float4*)&vc[dst] = vv;
    uint4 kr = { f2tf32(kv.x), f2tf32(kv.y), f2tf32(kv.z), f2tf32(kv.w) };
    uint4 vr = { f2tf32(vv.x), f2tf32(vv.y), f2tf32(vv.z), f2tf32(vv.w) };
    *(uint4*)&ktr[dst] = kr;
    *(uint4*)&vtr[dst] = vr;
}

// ---------------------------------------------------------------------------
// Tensor-core flash attention (operands pre-rounded; no CVT in MMA loops)
// CTA = (qtile 128, h, b). 256 thr, 8 warps; warp w owns rows [w*16, +16).
// K double-buffered; V prefetched during QK.
// ---------------------------------------------------------------------------
#define QP  132
#define KVP 136
#define PP  68

__global__ __launch_bounds__(256) void attn_tc(
    const float* __restrict__ kcache, const float* __restrict__ vcache)
{
    extern __shared__ unsigned smu[];
    unsigned* sQ = smu;                        // 128 x 132
    unsigned* sK = sQ + 128 * QP;              // 2 x 64 x 136
    unsigned* sV = sK + 2 * 64 * KVP;          // 64 x 136
    unsigned* sP = sV + 64 * KVP;              // 128 x 68

    const int qt = blockIdx.x, h = blockIdx.y, b = blockIdx.z;
    const int tid = threadIdx.x, lane = tid & 31, w = tid >> 5;
    const int g = lane >> 2, t = lane & 3;

    const float* kb = kcache + (size_t)(b * H_ + h) * S_ * D_;
    const float* vb = vcache + (size_t)(b * H_ + h) * S_ * D_;

    const int lr = tid >> 5;              // 0..7
    const int lc = (tid & 31) * 4;        // 0..124

#pragma unroll
    for (int l = 0; l < 8; l++) {
        int r = lr + l * 8;
        CP16(s2u(&sK[r * KVP + lc]), &kb[(size_t)r * D_ + lc]);
    }
    CP_COMMIT();

    // stage Q tile (already rounded+scaled): raw bit copy
#pragma unroll
    for (int l = 0; l < 16; l++) {
        int i = tid + l * 256;
        int r = i >> 5, c = (i & 31) * 4;
        uint4 qv = *(const uint4*)&g_q[(size_t)(b * T_ + qt * 128 + r) * E_ + h * D_ + c];
        *(uint4*)&sQ[r * QP + c] = qv;
    }

    float m0 = -1e30f, m1 = -1e30f, l0 = 0.f, l1 = 0.f;
    float acc_o[16][4];
#pragma unroll
    for (int nj = 0; nj < 16; nj++)
#pragma unroll
        for (int q = 0; q < 4; q++) acc_o[nj][q] = 0.f;

    for (int ci = 0; ci < S_ / 64; ci++) {
        const int cur = ci & 1;
        const unsigned* cK = sK + cur * 64 * KVP;

        CP_WAIT0();
        __syncthreads();

        // prefetch V_ci, then K_{ci+1}
        {
            const size_t vbase = (size_t)(ci * 64) * D_;
#pragma unroll
            for (int l = 0; l < 8; l++) {
                int r = lr + l * 8;
                CP16(s2u(&sV[r * KVP + lc]), &vb[vbase + (size_t)r * D_ + lc]);
            }
            CP_COMMIT();
        }
        if (ci + 1 < S_ / 64) {
            const size_t kbase = (size_t)((ci + 1) * 64) * D_;
            unsigned* nK = sK + (cur ^ 1) * 64 * KVP;
#pragma unroll
            for (int l = 0; l < 8; l++) {
                int r = lr + l * 8;
                CP16(s2u(&nK[r * KVP + lc]), &kb[kbase + (size_t)r * D_ + lc]);
            }
            CP_COMMIT();
        }

        // S = Q K^T
        float accs[8][4];
#pragma unroll
        for (int nj = 0; nj < 8; nj++)
#pragma unroll
            for (int q = 0; q < 4; q++) accs[nj][q] = 0.f;

#pragma unroll
        for (int ks = 0; ks < 16; ks++) {
            int r = w * 16 + g;
            unsigned a0 = sQ[r * QP + ks * 8 + t];
            unsigned a1 = sQ[(r + 8) * QP + ks * 8 + t];
            unsigned a2 = sQ[r * QP + ks * 8 + t + 4];
            unsigned a3 = sQ[(r + 8) * QP + ks * 8 + t + 4];
#pragma unroll
            for (int nj = 0; nj < 8; nj++) {
                unsigned b0 = cK[(nj * 8 + g) * KVP + ks * 8 + t];
                unsigned b1 = cK[(nj * 8 + g) * KVP + ks * 8 + t + 4];
                mma_tf32(accs[nj], a0, a1, a2, a3, b0, b1);
            }
        }

        // online softmax
        float rm0 = -1e30f, rm1 = -1e30f;
#pragma unroll
        for (int nj = 0; nj < 8; nj++) {
            rm0 = fmaxf(rm0, fmaxf(accs[nj][0], accs[nj][1]));
            rm1 = fmaxf(rm1, fmaxf(accs[nj][2], accs[nj][3]));
        }
        rm0 = fmaxf(rm0, __shfl_xor_sync(0xffffffffu, rm0, 1));
        rm0 = fmaxf(rm0, __shfl_xor_sync(0xffffffffu, rm0, 2));
        rm1 = fmaxf(rm1, __shfl_xor_sync(0xffffffffu, rm1, 1));
        rm1 = fmaxf(rm1, __shfl_xor_sync(0xffffffffu, rm1, 2));

        float nm0 = fmaxf(m0, rm0), nm1 = fmaxf(m1, rm1);
        float al0 = __expf(m0 - nm0), al1 = __expf(m1 - nm1);
        m0 = nm0; m1 = nm1;

        float sum0 = 0.f, sum1 = 0.f;
        int r0 = w * 16 + g;
#pragma unroll
        for (int nj = 0; nj < 8; nj++) {
            float p0 = __expf(accs[nj][0] - nm0);
            float p1 = __expf(accs[nj][1] - nm0);
            float p2 = __expf(accs[nj][2] - nm1);
            float p3 = __expf(accs[nj][3] - nm1);
            sum0 += p0 + p1;
            sum1 += p2 + p3;
            int c = nj * 8 + t * 2;
            uint2 u0 = { f2tf32(p0), f2tf32(p1) };
            uint2 u1 = { f2tf32(p2), f2tf32(p3) };
            *(uint2*)&sP[r0 * PP + c]       = u0;
            *(uint2*)&sP[(r0 + 8) * PP + c] = u1;
        }
        sum0 += __shfl_xor_sync(0xffffffffu, sum0, 1);
        sum0 += __shfl_xor_sync(0xffffffffu, sum0, 2);
        sum1 += __shfl_xor_sync(0xffffffffu, sum1, 1);
        sum1 += __shfl_xor_sync(0xffffffffu, sum1, 2);
        l0 = l0 * al0 + sum0;
        l1 = l1 * al1 + sum1;

#pragma unroll
        for (int nj = 0; nj < 16; nj++) {
            acc_o[nj][0] *= al0; acc_o[nj][1] *= al0;
            acc_o[nj][2] *= al1; acc_o[nj][3] *= al1;
        }

        if (ci + 1 < S_ / 64) { CP_WAIT1(); } else { CP_WAIT0(); }
        __syncthreads();

        // O += P V
#pragma unroll
        for (int ks = 0; ks < 8; ks++) {
            unsigned a0 = sP[(w * 16 + g) * PP + ks * 8 + t];
            unsigned a1 = sP[(w * 16 + g + 8) * PP + ks * 8 + t];
            unsigned a2 = sP[(w * 16 + g) * PP + ks * 8 + t + 4];
            unsigned a3 = sP[(w * 16 + g + 8) * PP + ks * 8 + t + 4];
#pragma unroll
            for (int nj = 0; nj < 16; nj++) {
                unsigned b0 = sV[(ks * 8 + t) * KVP + nj * 8 + g];
                unsigned b1 = sV[(ks * 8 + t + 4) * KVP + nj * 8 + g];
                mma_tf32(acc_o[nj], a0, a1, a2, a3, b0, b1);
            }
        }
    }

    // epilogue: normalize, round (so final GEMM needs no CVT), write
    float inv0 = 1.f / l0, inv1 = 1.f / l1;
    int row = b * T_ + qt * 128 + w * 16 + g;
#pragma unroll
    for (int nj = 0; nj < 16; nj++) {
        int col = h * D_ + nj * 8 + t * 2;
        uint2 v0 = { f2tf32(acc_o[nj][0] * inv0), f2tf32(acc_o[nj][1] * inv0) };
        uint2 v1 = { f2tf32(acc_o[nj][2] * inv1), f2tf32(acc_o[nj][3] * inv1) };
        *(uint2*)&g_attn[(size_t)row * E_ + col]       = v0;
        *(uint2*)&g_attn[(size_t)(row + 8) * E_ + col] = v1;
    }
}

// ---------------------------------------------------------------------------
extern "C" void kernel_launch(void* const* d_in, const int* in_sizes, int n_in,
                              void* d_out, int out_size)
{
    const float* x      = (const float*)d_in[0];
    const float* past_k = (const float*)d_in[1];
    const float* past_v = (const float*)d_in[2];
    const float* Wq     = (const float*)d_in[3];
    const float* bq     = (const float*)d_in[4];
    const float* Wk     = (const float*)d_in[5];
    const float* bk     = (const float*)d_in[6];
    const float* Wv     = (const float*)d_in[7];
    const float* bv     = (const float*)d_in[8];
    const float* Wo     = (const float*)d_in[9];
    const float* bo     = (const float*)d_in[10];

    float* out = (float*)d_out;                       // [B,T,E]
    float* kc  = out + (size_t)NTOK * E_;             // [B,H,S,D]
    float* vc  = kc + (size_t)CACHE_ELEMS;            // [B,H,S,D]

    void *pq, *pattn, *pxt, *pwq, *pwk, *pwv, *pwo, *pkt, *pvt;
    cudaGetSymbolAddress(&pq, g_q);
    cudaGetSymbolAddress(&pattn, g_attn);
    cudaGetSymbolAddress(&pxt, g_xt);
    cudaGetSymbolAddress(&pwq, g_wqt);
    cudaGetSymbolAddress(&pwk, g_wkt);
    cudaGetSymbolAddress(&pwv, g_wvt);
    cudaGetSymbolAddress(&pwo, g_wot);
    cudaGetSymbolAddress(&pkt, g_kt);
    cudaGetSymbolAddress(&pvt, g_vt);

    // pre-round operands to tf32 bits
    {
        int nx = NTOK * E_ / 4, nw = E_ * E_ / 4;
        round_tf32<<<(nx + 255) / 256, 256>>>(x,  (float*)pxt, nx);
        round_tf32<<<(nw + 255) / 256, 256>>>(Wq, (float*)pwq, nw);
        round_tf32<<<(nw + 255) / 256, 256>>>(Wk, (float*)pwk, nw);
        round_tf32<<<(nw + 255) / 256, 256>>>(Wv, (float*)pwv, nw);
        round_tf32<<<(nw + 255) / 256, 256>>>(Wo, (float*)pwo, nw);
    }

    // past copy (full cache + rounded shadow)
    {
        int total4 = B_ * H_ * TP_ * D_ / 4;
        copy_past<<<(total4 + 255) / 256, 256>>>(past_k, past_v, kc, vc,
                                                 (float*)pkt, (float*)pvt);
    }

    const size_t gemm_smem = (size_t)4 * 128 * GP * sizeof(float);
    cudaFuncSetAttribute(qkv_gemm,   cudaFuncAttributeMaxDynamicSharedMemorySize, (int)gemm_smem);
    cudaFuncSetAttribute(gemm_plain, cudaFuncAttributeMaxDynamicSharedMemorySize, (int)gemm_smem);

    // fused QKV projections
    dim3 gq(E_ / 128, NTOK / 128, 3);
    qkv_gemm<<<gq, 256, gemm_smem>>>((const float*)pxt, bq, bk, bv,
                                     (float*)pq, kc, vc,
                                     (float*)pkt, (float*)pvt);

    // attention (reads rounded shadows)
    size_t attn_smem = (size_t)(128 * QP + 3 * 64 * KVP + 128 * PP) * 4;
    cudaFuncSetAttribute(attn_tc, cudaFuncAttributeMaxDynamicSharedMemorySize, (int)attn_smem);
    attn_tc<<<dim3(T_ / 128, H_, B_), 256, attn_smem>>>((const float*)pkt, (const float*)pvt);

    // output projection
    dim3 gg(E_ / 128, NTOK / 128);
    gemm_plain<<<gg, 256, gemm_smem>>>((const float*)pattn, (const float*)pwo, bo, out);
}

// round 6
// speedup vs baseline: 3.2078x; 1.9428x over previous
#include <cuda_runtime.h>
#include <cuda_fp16.h>
#include <math.h>
#include <stdint.h>

// Problem constants
#define E_   2048
#define H_   16
#define D_   128
#define B_   4
#define T_   1024
#define TP_  3072
#define S_   (TP_ + T_)      // 4096
#define NTOK (B_ * T_)       // 4096
#define CACHE_ELEMS (B_ * H_ * S_ * D_)   // 33.5M
#define QSCALE 0.08838834764831845f       // 1/sqrt(128)

// Scratch (device globals -- no allocations allowed)
__device__ __half g_xh[NTOK * E_];     // x in fp16
__device__ __half g_wqh[E_ * E_];
__device__ __half g_wkh[E_ * E_];
__device__ __half g_wvh[E_ * E_];
__device__ __half g_woh[E_ * E_];
__device__ __half g_qh[NTOK * E_];     // Q (scaled) fp16
__device__ __half g_ah[NTOK * E_];     // attention output fp16
__device__ __half g_kh[CACHE_ELEMS];   // K cache shadow fp16 [b,h,s,d]
__device__ __half g_vh[CACHE_ELEMS];   // V cache shadow fp16 [b,h,s,d]

// ---------------------------------------------------------------------------
// Helpers
// ---------------------------------------------------------------------------
__device__ __forceinline__ void mma_f16(float c[4],
    unsigned a0, unsigned a1, unsigned a2, unsigned a3,
    unsigned b0, unsigned b1)
{
    asm volatile(
        "mma.sync.aligned.m16n8k16.row.col.f32.f16.f16.f32 "
        "{%0,%1,%2,%3}, {%4,%5,%6,%7}, {%8,%9}, {%0,%1,%2,%3};"
        : "+f"(c[0]), "+f"(c[1]), "+f"(c[2]), "+f"(c[3])
        : "r"(a0), "r"(a1), "r"(a2), "r"(a3), "r"(b0), "r"(b1));
}

__device__ __forceinline__ unsigned s2u(const void* p) {
    return (unsigned)__cvta_generic_to_shared(p);
}

__device__ __forceinline__ unsigned h2u(float x, float y) {
    __half2 h = __floats2half2_rn(x, y);
    return *(unsigned*)&h;
}

#define CP16(dst_u32, src_ptr) \
    asm volatile("cp.async.cg.shared.global [%0], [%1], 16;" :: "r"(dst_u32), "l"(src_ptr))
#define CP_COMMIT() asm volatile("cp.async.commit_group;")
#define CP_WAIT0()  asm volatile("cp.async.wait_group 0;")
#define CP_WAIT1()  asm volatile("cp.async.wait_group 1;")

__device__ __forceinline__ void ldm_x4_trans(unsigned r[4], unsigned addr) {
    asm volatile(
        "ldmatrix.sync.aligned.m8n8.x4.trans.shared.b16 {%0,%1,%2,%3}, [%4];"
        : "=r"(r[0]), "=r"(r[1]), "=r"(r[2]), "=r"(r[3]) : "r"(addr));
}

// ---------------------------------------------------------------------------
// fp32 -> fp16 conversion pass
// ---------------------------------------------------------------------------
__global__ void to_half(const float* __restrict__ src,
                        __half* __restrict__ dst, int n4)
{
    int i = blockIdx.x * blockDim.x + threadIdx.x;
    if (i >= n4) return;
    float4 v = ((const float4*)src)[i];
    uint2 u = { h2u(v.x, v.y), h2u(v.z, v.w) };
    ((uint2*)dst)[i] = u;
}

// ---------------------------------------------------------------------------
// fp16 tensor-core GEMM: C[n,m] = A[n,:] . W[m,:] + bias[m]
// Block 128x128, BK=64 halfs, 8 warps (4x2), warp tile 32x64.
// 2-stage cp.async pipeline. smem pitch 72 halfs (conflict-free: bank 4g+t).
// mode = base_mode + blockIdx.z: 0=Q, 1=K, 2=V, 3=O-proj.
// ---------------------------------------------------------------------------
#define GAP 72
#define HA  (128 * GAP)     // halfs per buffer (9216)
#define GEMM_SMEM (4 * HA * 2)  // 73728 bytes

__global__ __launch_bounds__(256, 2) void gemm_h(
    int base_mode,
    const float* __restrict__ bq, const float* __restrict__ bk,
    const float* __restrict__ bv, const float* __restrict__ bo,
    float* __restrict__ kc, float* __restrict__ vc, float* __restrict__ outp)
{
    extern __shared__ __half sh[];
    __half* bufA[2] = { sh,          sh + 2 * HA };
    __half* bufB[2] = { sh + HA,     sh + 3 * HA };

    const int mode = base_mode + blockIdx.z;
    const __half* A    = (mode < 3) ? g_xh : g_ah;
    const __half* W    = (mode == 0) ? g_wqh : (mode == 1) ? g_wkh
                        : (mode == 2) ? g_wvh : g_woh;
    const float* bias  = (mode == 0) ? bq : (mode == 1) ? bk
                        : (mode == 2) ? bv : bo;

    const int tid  = threadIdx.x;
    const int lane = tid & 31, wid = tid >> 5;
    const int wm = wid >> 1, wn = wid & 1;
    const int g = lane >> 2, t = lane & 3;
    const int brow = blockIdx.y * 128, bcol = blockIdx.x * 128;

    const int lr = tid >> 3;            // 0..127 over 2 iters? no: idx>>3
    const int lc = (tid & 7) * 8;       // 0..56 halfs

    float acc[2][8][4];
#pragma unroll
    for (int mi = 0; mi < 2; mi++)
#pragma unroll
        for (int nj = 0; nj < 8; nj++)
#pragma unroll
            for (int q = 0; q < 4; q++) acc[mi][nj][q] = 0.f;

    // prologue: buffer 0 (k0 = 0)
#pragma unroll
    for (int l = 0; l < 4; l++) {
        int idx = tid + l * 256;
        int r = idx >> 3, c = (idx & 7) * 8;
        CP16(s2u(&bufA[0][r * GAP + c]), &A[(size_t)(brow + r) * E_ + c]);
        CP16(s2u(&bufB[0][r * GAP + c]), &W[(size_t)(bcol + r) * E_ + c]);
    }
    CP_COMMIT();

    const int KT = E_ / 64;  // 32
    for (int kt = 0; kt < KT; kt++) {
        const int cur = kt & 1;
        CP_WAIT0();
        __syncthreads();
        if (kt + 1 < KT) {
            const int k0 = (kt + 1) * 64;
#pragma unroll
            for (int l = 0; l < 4; l++) {
                int idx = tid + l * 256;
                int r = idx >> 3, c = (idx & 7) * 8;
                CP16(s2u(&bufA[cur ^ 1][r * GAP + c]), &A[(size_t)(brow + r) * E_ + k0 + c]);
                CP16(s2u(&bufB[cur ^ 1][r * GAP + c]), &W[(size_t)(bcol + r) * E_ + k0 + c]);
            }
            CP_COMMIT();
        }

        const __half* cA = bufA[cur];
        const __half* cB = bufB[cur];
#pragma unroll
        for (int ks = 0; ks < 4; ks++) {
            unsigned a[2][4];
#pragma unroll
            for (int mi = 0; mi < 2; mi++) {
                int r = wm * 32 + mi * 16 + g;
                a[mi][0] = *(const unsigned*)&cA[r * GAP + ks * 16 + 2 * t];
                a[mi][1] = *(const unsigned*)&cA[(r + 8) * GAP + ks * 16 + 2 * t];
                a[mi][2] = *(const unsigned*)&cA[r * GAP + ks * 16 + 2 * t + 8];
                a[mi][3] = *(const unsigned*)&cA[(r + 8) * GAP + ks * 16 + 2 * t + 8];
            }
#pragma unroll
            for (int nj = 0; nj < 8; nj++) {
                int n = wn * 64 + nj * 8 + g;
                unsigned b0 = *(const unsigned*)&cB[n * GAP + ks * 16 + 2 * t];
                unsigned b1 = *(const unsigned*)&cB[n * GAP + ks * 16 + 2 * t + 8];
                mma_f16(acc[0][nj], a[0][0], a[0][1], a[0][2], a[0][3], b0, b1);
                mma_f16(acc[1][nj], a[1][0], a[1][1], a[1][2], a[1][3], b0, b1);
            }
        }
    }
    __syncthreads();

    // epilogue
#pragma unroll
    for (int mi = 0; mi < 2; mi++) {
#pragma unroll
        for (int nj = 0; nj < 8; nj++) {
            int row = brow + wm * 32 + mi * 16 + g;
            int col = bcol + wn * 64 + nj * 8 + 2 * t;
            float b0 = bias[col], b1 = bias[col + 1];
            float v00 = acc[mi][nj][0] + b0, v01 = acc[mi][nj][1] + b1;
            float v10 = acc[mi][nj][2] + b0, v11 = acc[mi][nj][3] + b1;
            if (mode == 0) {
                *(unsigned*)&g_qh[(size_t)row * E_ + col] =
                    h2u(v00 * QSCALE, v01 * QSCALE);
                *(unsigned*)&g_qh[(size_t)(row + 8) * E_ + col] =
                    h2u(v10 * QSCALE, v11 * QSCALE);
            } else if (mode == 3) {
                float2 f0 = { v00, v01 }, f1 = { v10, v11 };
                *(float2*)&outp[(size_t)row * E_ + col]       = f0;
                *(float2*)&outp[(size_t)(row + 8) * E_ + col] = f1;
            } else {
                float* dst   = (mode == 1) ? kc  : vc;
                __half* dstH = (mode == 1) ? g_kh : g_vh;
                int b_i = row >> 10, t_i = row & 1023;
                int h_i = col >> 7,  d_i = col & 127;
                size_t base = ((size_t)(b_i * H_ + h_i) * S_ + TP_ + t_i) * D_ + d_i;
                float2 f0 = { v00, v01 }, f1 = { v10, v11 };
                *(float2*)&dst[base]             = f0;
                *(float2*)&dst[base + 8ull * D_] = f1;
                *(unsigned*)&dstH[base]             = h2u(v00, v01);
                *(unsigned*)&dstH[base + 8ull * D_] = h2u(v10, v11);
            }
        }
    }
}

// ---------------------------------------------------------------------------
// Copy past K/V into fp32 cache + fp16 shadow
// ---------------------------------------------------------------------------
__global__ void copy_past(const float* __restrict__ pk,
                          const float* __restrict__ pv,
                          float* __restrict__ kc, float* __restrict__ vc)
{
    int idx = blockIdx.x * blockDim.x + threadIdx.x;   // float4 index
    const int total4 = B_ * H_ * TP_ * D_ / 4;
    if (idx >= total4) return;
    int bh  = idx / (TP_ * D_ / 4);
    int off = (idx % (TP_ * D_ / 4)) * 4;
    size_t dst = (size_t)bh * S_ * D_ + off;
    float4 kv = *(const float4*)&pk[(size_t)idx * 4];
    float4 vv = *(const float4*)&pv[(size_t)idx * 4];
    *(float4*)&kc[dst] = kv;
    *(float4*)&vc[dst] = vv;
    uint2 kh = { h2u(kv.x, kv.y), h2u(kv.z, kv.w) };
    uint2 vh = { h2u(vv.x, vv.y), h2u(vv.z, vv.w) };
    *(uint2*)&g_kh[dst] = kh;
    *(uint2*)&g_vh[dst] = vh;
}

// ---------------------------------------------------------------------------
// fp16 tensor-core flash attention.
// CTA = (qtile 128, h, b). 256 thr, 8 warps; warp w owns rows [w*16, +16).
// K double-buffered via cp.async; V prefetched during QK.
// V b-fragments via ldmatrix.x4.trans. All smem pitches conflict-free.
// ---------------------------------------------------------------------------
#define QPH 136
#define KPH 136
#define VPH 136
#define PPH 72
// smem halfs: sQ 128*136, sK 2*64*136, sV 64*136, sP 128*72
#define ATTN_SMEM ((128*QPH + 2*64*KPH + 64*VPH + 128*PPH) * 2)

__global__ __launch_bounds__(256) void attn_h(void)
{
    extern __shared__ __half sm[];
    __half* sQ = sm;                         // 128 x 136
    __half* sK = sQ + 128 * QPH;             // 2 x 64 x 136
    __half* sV = sK + 2 * 64 * KPH;          // 64 x 136
    __half* sP = sV + 64 * VPH;              // 128 x 72

    const int qt = blockIdx.x, h = blockIdx.y, b = blockIdx.z;
    const int tid = threadIdx.x, lane = tid & 31, w = tid >> 5;
    const int g = lane >> 2, t = lane & 3;

    const __half* kb = g_kh + (size_t)(b * H_ + h) * S_ * D_;
    const __half* vb = g_vh + (size_t)(b * H_ + h) * S_ * D_;

    // prologue: prefetch K chunk 0 (64 x 128 halfs)
#pragma unroll
    for (int l = 0; l < 4; l++) {
        int idx = tid + l * 256;
        int r = idx >> 4, c = (idx & 15) * 8;
        CP16(s2u(&sK[r * KPH + c]), &kb[(size_t)r * D_ + c]);
    }
    CP_COMMIT();

    // stage Q tile (fp16, already scaled)
#pragma unroll
    for (int l = 0; l < 8; l++) {
        int idx = tid + l * 256;
        int r = idx >> 4, c = (idx & 15) * 8;
        uint4 qv = *(const uint4*)&g_qh[(size_t)(b * T_ + qt * 128 + r) * E_ + h * D_ + c];
        *(uint4*)&sQ[r * QPH + c] = qv;
    }

    float m0 = -1e30f, m1 = -1e30f, l0 = 0.f, l1 = 0.f;
    float acc_o[16][4];
#pragma unroll
    for (int nj = 0; nj < 16; nj++)
#pragma unroll
        for (int q = 0; q < 4; q++) acc_o[nj][q] = 0.f;

    for (int ci = 0; ci < S_ / 64; ci++) {
        const int cur = ci & 1;
        const __half* cK = sK + cur * 64 * KPH;

        CP_WAIT0();
        __syncthreads();

        // prefetch V_ci, then K_{ci+1}
        {
            const size_t vbase = (size_t)(ci * 64) * D_;
#pragma unroll
            for (int l = 0; l < 4; l++) {
                int idx = tid + l * 256;
                int r = idx >> 4, c = (idx & 15) * 8;
                CP16(s2u(&sV[r * VPH + c]), &vb[vbase + (size_t)r * D_ + c]);
            }
            CP_COMMIT();
        }
        if (ci + 1 < S_ / 64) {
            const size_t kbase = (size_t)((ci + 1) * 64) * D_;
            __half* nK = sK + (cur ^ 1) * 64 * KPH;
#pragma unroll
            for (int l = 0; l < 4; l++) {
                int idx = tid + l * 256;
                int r = idx >> 4, c = (idx & 15) * 8;
                CP16(s2u(&nK[r * KPH + c]), &kb[kbase + (size_t)r * D_ + c]);
            }
            CP_COMMIT();
        }

        // S = Q K^T   (warp: 16 q-rows x 64 keys, K=128 -> 8 k-steps)
        float accs[8][4];
#pragma unroll
        for (int nj = 0; nj < 8; nj++)
#pragma unroll
            for (int q = 0; q < 4; q++) accs[nj][q] = 0.f;

#pragma unroll
        for (int ks = 0; ks < 8; ks++) {
            int r = w * 16 + g;
            unsigned a0 = *(const unsigned*)&sQ[r * QPH + ks * 16 + 2 * t];
            unsigned a1 = *(const unsigned*)&sQ[(r + 8) * QPH + ks * 16 + 2 * t];
            unsigned a2 = *(const unsigned*)&sQ[r * QPH + ks * 16 + 2 * t + 8];
            unsigned a3 = *(const unsigned*)&sQ[(r + 8) * QPH + ks * 16 + 2 * t + 8];
#pragma unroll
            for (int nj = 0; nj < 8; nj++) {
                unsigned b0 = *(const unsigned*)&cK[(nj * 8 + g) * KPH + ks * 16 + 2 * t];
                unsigned b1 = *(const unsigned*)&cK[(nj * 8 + g) * KPH + ks * 16 + 2 * t + 8];
                mma_f16(accs[nj], a0, a1, a2, a3, b0, b1);
            }
        }

        // online softmax
        float rm0 = -1e30f, rm1 = -1e30f;
#pragma unroll
        for (int nj = 0; nj < 8; nj++) {
            rm0 = fmaxf(rm0, fmaxf(accs[nj][0], accs[nj][1]));
            rm1 = fmaxf(rm1, fmaxf(accs[nj][2], accs[nj][3]));
        }
        rm0 = fmaxf(rm0, __shfl_xor_sync(0xffffffffu, rm0, 1));
        rm0 = fmaxf(rm0, __shfl_xor_sync(0xffffffffu, rm0, 2));
        rm1 = fmaxf(rm1, __shfl_xor_sync(0xffffffffu, rm1, 1));
        rm1 = fmaxf(rm1, __shfl_xor_sync(0xffffffffu, rm1, 2));

        float nm0 = fmaxf(m0, rm0), nm1 = fmaxf(m1, rm1);
        float al0 = __expf(m0 - nm0), al1 = __expf(m1 - nm1);
        m0 = nm0; m1 = nm1;

        float sum0 = 0.f, sum1 = 0.f;
        int r0 = w * 16 + g;
#pragma unroll
        for (int nj = 0; nj < 8; nj++) {
            float p0 = __expf(accs[nj][0] - nm0);
            float p1 = __expf(accs[nj][1] - nm0);
            float p2 = __expf(accs[nj][2] - nm1);
            float p3 = __expf(accs[nj][3] - nm1);
            sum0 += p0 + p1;
            sum1 += p2 + p3;
            int c = nj * 8 + 2 * t;
            *(unsigned*)&sP[r0 * PPH + c]       = h2u(p0, p1);
            *(unsigned*)&sP[(r0 + 8) * PPH + c] = h2u(p2, p3);
        }
        sum0 += __shfl_xor_sync(0xffffffffu, sum0, 1);
        sum0 += __shfl_xor_sync(0xffffffffu, sum0, 2);
        sum1 += __shfl_xor_sync(0xffffffffu, sum1, 1);
        sum1 += __shfl_xor_sync(0xffffffffu, sum1, 2);
        l0 = l0 * al0 + sum0;
        l1 = l1 * al1 + sum1;

#pragma unroll
        for (int nj = 0; nj < 16; nj++) {
            acc_o[nj][0] *= al0; acc_o[nj][1] *= al0;
            acc_o[nj][2] *= al1; acc_o[nj][3] *= al1;
        }

        if (ci + 1 < S_ / 64) { CP_WAIT1(); } else { CP_WAIT0(); }
        __syncthreads();

        // O += P V   (V b-frags via ldmatrix.trans on row-major sV)
#pragma unroll
        for (int ks = 0; ks < 4; ks++) {
            unsigned a0 = *(const unsigned*)&sP[(w * 16 + g) * PPH + ks * 16 + 2 * t];
            unsigned a1 = *(const unsigned*)&sP[(w * 16 + g + 8) * PPH + ks * 16 + 2 * t];
            unsigned a2 = *(const unsigned*)&sP[(w * 16 + g) * PPH + ks * 16 + 2 * t + 8];
            unsigned a3 = *(const unsigned*)&sP[(w * 16 + g + 8) * PPH + ks * 16 + 2 * t + 8];
            int key = ks * 16 + (lane & 15);
#pragma unroll
            for (int nj2 = 0; nj2 < 8; nj2++) {
                int dd = nj2 * 16 + (lane >> 4) * 8;
                unsigned bb[4];
                ldm_x4_trans(bb, s2u(&sV[key * VPH + dd]));
                mma_f16(acc_o[nj2 * 2],     a0, a1, a2, a3, bb[0], bb[1]);
                mma_f16(acc_o[nj2 * 2 + 1], a0, a1, a2, a3, bb[2], bb[3]);
            }
        }
    }

    // epilogue: normalize, write fp16 to g_ah
    float inv0 = 1.f / l0, inv1 = 1.f / l1;
    int row = b * T_ + qt * 128 + w * 16 + g;
#pragma unroll
    for (int nj = 0; nj < 16; nj++) {
        int col = h * D_ + nj * 8 + 2 * t;
        *(unsigned*)&g_ah[(size_t)row * E_ + col] =
            h2u(acc_o[nj][0] * inv0, acc_o[nj][1] * inv0);
        *(unsigned*)&g_ah[(size_t)(row + 8) * E_ + col] =
            h2u(acc_o[nj][2] * inv1, acc_o[nj][3] * inv1);
    }
}

// ---------------------------------------------------------------------------
extern "C" void kernel_launch(void* const* d_in, const int* in_sizes, int n_in,
                              void* d_out, int out_size)
{
    const float* x      = (const float*)d_in[0];
    const float* past_k = (const float*)d_in[1];
    const float* past_v = (const float*)d_in[2];
    const float* Wq     = (const float*)d_in[3];
    const float* bq     = (const float*)d_in[4];
    const float* Wk     = (const float*)d_in[5];
    const float* bk     = (const float*)d_in[6];
    const float* Wv     = (const float*)d_in[7];
    const float* bv     = (const float*)d_in[8];
    const float* Wo     = (const float*)d_in[9];
    const float* bo     = (const float*)d_in[10];

    float* out = (float*)d_out;                       // [B,T,E]
    float* kc  = out + (size_t)NTOK * E_;             // [B,H,S,D]
    float* vc  = kc + (size_t)CACHE_ELEMS;            // [B,H,S,D]

    void *pxh, *pwq, *pwk, *pwv, *pwo;
    cudaGetSymbolAddress(&pxh, g_xh);
    cudaGetSymbolAddress(&pwq, g_wqh);
    cudaGetSymbolAddress(&pwk, g_wkh);
    cudaGetSymbolAddress(&pwv, g_wvh);
    cudaGetSymbolAddress(&pwo, g_woh);

    // fp32 -> fp16 conversion of x and weights
    {
        int nx = NTOK * E_ / 4, nw = E_ * E_ / 4;
        to_half<<<(nx + 255) / 256, 256>>>(x,  (__half*)pxh, nx);
        to_half<<<(nw + 255) / 256, 256>>>(Wq, (__half*)pwq, nw);
        to_half<<<(nw + 255) / 256, 256>>>(Wk, (__half*)pwk, nw);
        to_half<<<(nw + 255) / 256, 256>>>(Wv, (__half*)pwv, nw);
        to_half<<<(nw + 255) / 256, 256>>>(Wo, (__half*)pwo, nw);
    }

    // past copy (fp32 cache + fp16 shadows)
    {
        int total4 = B_ * H_ * TP_ * D_ / 4;
        copy_past<<<(total4 + 255) / 256, 256>>>(past_k, past_v, kc, vc);
    }

    cudaFuncSetAttribute(gemm_h, cudaFuncAttributeMaxDynamicSharedMemorySize, GEMM_SMEM);
    cudaFuncSetAttribute(attn_h, cudaFuncAttributeMaxDynamicSharedMemorySize, ATTN_SMEM);

    // fused QKV projections
    dim3 gq(E_ / 128, NTOK / 128, 3);
    gemm_h<<<gq, 256, GEMM_SMEM>>>(0, bq, bk, bv, bo, kc, vc, out);

    // attention
    attn_h<<<dim3(T_ / 128, H_, B_), 256, ATTN_SMEM>>>();

    // output projection
    dim3 go(E_ / 128, NTOK / 128, 1);
    gemm_h<<<go, 256, GEMM_SMEM>>>(3, bq, bk, bv, bo, kc, vc, out);
}

// round 8
// speedup vs baseline: 3.4139x; 1.0643x over previous
#include <cuda_runtime.h>
#include <cuda_fp16.h>
#include <math.h>
#include <stdint.h>

// Problem constants
#define E_   2048
#define H_   16
#define D_   128
#define B_   4
#define T_   1024
#define TP_  3072
#define S_   (TP_ + T_)      // 4096
#define NTOK (B_ * T_)       // 4096
#define CACHE_ELEMS (B_ * H_ * S_ * D_)   // 33.5M
#define QSCALE 0.08838834764831845f       // 1/sqrt(128)

// Scratch (device globals -- no allocations allowed)
__device__ __half g_xh[NTOK * E_];     // x in fp16
__device__ __half g_wqh[E_ * E_];
__device__ __half g_wkh[E_ * E_];
__device__ __half g_wvh[E_ * E_];
__device__ __half g_woh[E_ * E_];
__device__ __half g_qh[NTOK * E_];     // Q (scaled) fp16
__device__ __half g_ah[NTOK * E_];     // attention output fp16
__device__ __half g_kh[CACHE_ELEMS];   // K cache shadow fp16 [b,h,s,d]
__device__ __half g_vh[CACHE_ELEMS];   // V cache shadow fp16 [b,h,s,d]

// ---------------------------------------------------------------------------
// Helpers
// ---------------------------------------------------------------------------
__device__ __forceinline__ void mma_f16(float c[4],
    unsigned a0, unsigned a1, unsigned a2, unsigned a3,
    unsigned b0, unsigned b1)
{
    asm volatile(
        "mma.sync.aligned.m16n8k16.row.col.f32.f16.f16.f32 "
        "{%0,%1,%2,%3}, {%4,%5,%6,%7}, {%8,%9}, {%0,%1,%2,%3};"
        : "+f"(c[0]), "+f"(c[1]), "+f"(c[2]), "+f"(c[3])
        : "r"(a0), "r"(a1), "r"(a2), "r"(a3), "r"(b0), "r"(b1));
}

__device__ __forceinline__ unsigned s2u(const void* p) {
    return (unsigned)__cvta_generic_to_shared(p);
}

__device__ __forceinline__ unsigned h2u(float x, float y) {
    __half2 h = __floats2half2_rn(x, y);
    return *(unsigned*)&h;
}

#define CP16(dst_u32, src_ptr) \
    asm volatile("cp.async.cg.shared.global [%0], [%1], 16;" :: "r"(dst_u32), "l"(src_ptr))
#define CP_COMMIT() asm volatile("cp.async.commit_group;")
#define CP_WAIT0()  asm volatile("cp.async.wait_group 0;")
#define CP_WAIT1()  asm volatile("cp.async.wait_group 1;")

__device__ __forceinline__ void ldm_x4_trans(unsigned r[4], unsigned addr) {
    asm volatile(
        "ldmatrix.sync.aligned.m8n8.x4.trans.shared.b16 {%0,%1,%2,%3}, [%4];"
        : "=r"(r[0]), "=r"(r[1]), "=r"(r[2]), "=r"(r[3]) : "r"(addr));
}

// ---------------------------------------------------------------------------
// Fused fp32 -> fp16 conversion (x + 4 weights in one launch)
// blockIdx.y: 0=x, 1=Wq, 2=Wk, 3=Wv, 4=Wo
// ---------------------------------------------------------------------------
__global__ void to_half_all(const float* __restrict__ x,
                            const float* __restrict__ wq,
                            const float* __restrict__ wk,
                            const float* __restrict__ wv,
                            const float* __restrict__ wo)
{
    const int z = blockIdx.y;
    const float* src = (z == 0) ? x : (z == 1) ? wq : (z == 2) ? wk
                      : (z == 3) ? wv : wo;
    __half* dst = (z == 0) ? g_xh : (z == 1) ? g_wqh : (z == 2) ? g_wkh
                 : (z == 3) ? g_wvh : g_woh;
    const int n4 = (z == 0) ? NTOK * E_ / 4 : E_ * E_ / 4;
    for (int i = blockIdx.x * blockDim.x + threadIdx.x; i < n4;
         i += gridDim.x * blockDim.x) {
        float4 v = ((const float4*)src)[i];
        uint2 u = { h2u(v.x, v.y), h2u(v.z, v.w) };
        ((uint2*)dst)[i] = u;
    }
}

// ---------------------------------------------------------------------------
// fp16 tensor-core GEMM + fused past-KV copy.
// mode = base_mode + blockIdx.z:
//   0=Q-proj, 1=K-proj, 2=V-proj, 3=past-KV copy, 4=O-proj.
// Launch 1: base_mode=0, z in 0..3 (QKV GEMMs + copy overlap).
// Launch 2: base_mode=4, z=0 (O-proj).
// Block 128x128, BK=64 halfs, 8 warps (4x2), 2-stage cp.async pipeline.
// ---------------------------------------------------------------------------
#define GAP 72
#define HA  (128 * GAP)         // halfs per buffer (9216)
#define GEMM_SMEM (4 * HA * 2)  // 73728 bytes

__global__ __launch_bounds__(256, 2) void gemm_h(
    int base_mode,
    const float* __restrict__ bq, const float* __restrict__ bk,
    const float* __restrict__ bv, const float* __restrict__ bo,
    const float* __restrict__ past_k, const float* __restrict__ past_v,
    float* __restrict__ kc, float* __restrict__ vc, float* __restrict__ outp)
{
    const int mode = base_mode + blockIdx.z;

    if (mode == 3) {
        // ---- past copy CTAs (grid-stride over float4s) ----
        const int total4 = B_ * H_ * TP_ * D_ / 4;
        const int nct = gridDim.x * gridDim.y;        // 512
        const int cta = blockIdx.y * gridDim.x + blockIdx.x;
        for (int idx = cta * 256 + threadIdx.x; idx < total4; idx += nct * 256) {
            int bh  = idx / (TP_ * D_ / 4);
            int off = (idx % (TP_ * D_ / 4)) * 4;
            size_t dst = (size_t)bh * S_ * D_ + off;
            float4 kv = *(const float4*)&past_k[(size_t)idx * 4];
            float4 vv = *(const float4*)&past_v[(size_t)idx * 4];
            *(float4*)&kc[dst] = kv;
            *(float4*)&vc[dst] = vv;
            uint2 kh = { h2u(kv.x, kv.y), h2u(kv.z, kv.w) };
            uint2 vh = { h2u(vv.x, vv.y), h2u(vv.z, vv.w) };
            *(uint2*)&g_kh[dst] = kh;
            *(uint2*)&g_vh[dst] = vh;
        }
        return;
    }

    extern __shared__ __half sh[];
    __half* bufA[2] = { sh,      sh + 2 * HA };
    __half* bufB[2] = { sh + HA, sh + 3 * HA };

    const __half* A    = (mode < 3) ? g_xh : g_ah;
    const __half* W    = (mode == 0) ? g_wqh : (mode == 1) ? g_wkh
                        : (mode == 2) ? g_wvh : g_woh;
    const float* bias  = (mode == 0) ? bq : (mode == 1) ? bk
                        : (mode == 2) ? bv : bo;

    const int tid  = threadIdx.x;
    const int lane = tid & 31, wid = tid >> 5;
    const int wm = wid >> 1, wn = wid & 1;
    const int g = lane >> 2, t = lane & 3;
    const int brow = blockIdx.y * 128, bcol = blockIdx.x * 128;

    float acc[2][8][4];
#pragma unroll
    for (int mi = 0; mi < 2; mi++)
#pragma unroll
        for (int nj = 0; nj < 8; nj++)
#pragma unroll
            for (int q = 0; q < 4; q++) acc[mi][nj][q] = 0.f;

    // prologue: buffer 0 (k0 = 0)
#pragma unroll
    for (int l = 0; l < 4; l++) {
        int idx = tid + l * 256;
        int r = idx >> 3, c = (idx & 7) * 8;
        CP16(s2u(&bufA[0][r * GAP + c]), &A[(size_t)(brow + r) * E_ + c]);
        CP16(s2u(&bufB[0][r * GAP + c]), &W[(size_t)(bcol + r) * E_ + c]);
    }
    CP_COMMIT();

    const int KT = E_ / 64;  // 32
    for (int kt = 0; kt < KT; kt++) {
        const int cur = kt & 1;
        CP_WAIT0();
        __syncthreads();
        if (kt + 1 < KT) {
            const int k0 = (kt + 1) * 64;
#pragma unroll
            for (int l = 0; l < 4; l++) {
                int idx = tid + l * 256;
                int r = idx >> 3, c = (idx & 7) * 8;
                CP16(s2u(&bufA[cur ^ 1][r * GAP + c]), &A[(size_t)(brow + r) * E_ + k0 + c]);
                CP16(s2u(&bufB[cur ^ 1][r * GAP + c]), &W[(size_t)(bcol + r) * E_ + k0 + c]);
            }
            CP_COMMIT();
        }

        const __half* cA = bufA[cur];
        const __half* cB = bufB[cur];
#pragma unroll
        for (int ks = 0; ks < 4; ks++) {
            unsigned a[2][4];
#pragma unroll
            for (int mi = 0; mi < 2; mi++) {
                int r = wm * 32 + mi * 16 + g;
                a[mi][0] = *(const unsigned*)&cA[r * GAP + ks * 16 + 2 * t];
                a[mi][1] = *(const unsigned*)&cA[(r + 8) * GAP + ks * 16 + 2 * t];
                a[mi][2] = *(const unsigned*)&cA[r * GAP + ks * 16 + 2 * t + 8];
                a[mi][3] = *(const unsigned*)&cA[(r + 8) * GAP + ks * 16 + 2 * t + 8];
            }
#pragma unroll
            for (int nj = 0; nj < 8; nj++) {
                int n = wn * 64 + nj * 8 + g;
                unsigned b0 = *(const unsigned*)&cB[n * GAP + ks * 16 + 2 * t];
                unsigned b1 = *(const unsigned*)&cB[n * GAP + ks * 16 + 2 * t + 8];
                mma_f16(acc[0][nj], a[0][0], a[0][1], a[0][2], a[0][3], b0, b1);
                mma_f16(acc[1][nj], a[1][0], a[1][1], a[1][2], a[1][3], b0, b1);
            }
        }
    }
    __syncthreads();

    // epilogue
#pragma unroll
    for (int mi = 0; mi < 2; mi++) {
#pragma unroll
        for (int nj = 0; nj < 8; nj++) {
            int row = brow + wm * 32 + mi * 16 + g;
            int col = bcol + wn * 64 + nj * 8 + 2 * t;
            float b0 = bias[col], b1 = bias[col + 1];
            float v00 = acc[mi][nj][0] + b0, v01 = acc[mi][nj][1] + b1;
            float v10 = acc[mi][nj][2] + b0, v11 = acc[mi][nj][3] + b1;
            if (mode == 0) {
                *(unsigned*)&g_qh[(size_t)row * E_ + col] =
                    h2u(v00 * QSCALE, v01 * QSCALE);
                *(unsigned*)&g_qh[(size_t)(row + 8) * E_ + col] =
                    h2u(v10 * QSCALE, v11 * QSCALE);
            } else if (mode == 4) {
                float2 f0 = { v00, v01 }, f1 = { v10, v11 };
                *(float2*)&outp[(size_t)row * E_ + col]       = f0;
                *(float2*)&outp[(size_t)(row + 8) * E_ + col] = f1;
            } else {
                float* dst   = (mode == 1) ? kc  : vc;
                __half* dstH = (mode == 1) ? g_kh : g_vh;
                int b_i = row >> 10, t_i = row & 1023;
                int h_i = col >> 7,  d_i = col & 127;
                size_t base = ((size_t)(b_i * H_ + h_i) * S_ + TP_ + t_i) * D_ + d_i;
                float2 f0 = { v00, v01 }, f1 = { v10, v11 };
                *(float2*)&dst[base]             = f0;
                *(float2*)&dst[base + 8ull * D_] = f1;
                *(unsigned*)&dstH[base]             = h2u(v00, v01);
                *(unsigned*)&dstH[base + 8ull * D_] = h2u(v10, v11);
            }
        }
    }
}

// ---------------------------------------------------------------------------
// fp16 tensor-core flash attention. 2 CTAs/SM (smem 103KB, regs capped 128).
// CTA = (qtile 128, h, b). 256 thr, 8 warps; warp w owns rows [w*16, +16).
// K double-buffered via cp.async; V prefetched during QK.
// V b-fragments via ldmatrix.x4.trans.
// ---------------------------------------------------------------------------
#define QPH 136
#define KPH 136
#define VPH 136
#define PPH 72
#define ATTN_SMEM ((128*QPH + 2*64*KPH + 64*VPH + 128*PPH) * 2)

__global__ __launch_bounds__(256, 2) void attn_h(void)
{
    extern __shared__ __half sm[];
    __half* sQ = sm;                         // 128 x 136
    __half* sK = sQ + 128 * QPH;             // 2 x 64 x 136
    __half* sV = sK + 2 * 64 * KPH;          // 64 x 136
    __half* sP = sV + 64 * VPH;              // 128 x 72

    const int qt = blockIdx.x, h = blockIdx.y, b = blockIdx.z;
    const int tid = threadIdx.x, lane = tid & 31, w = tid >> 5;
    const int g = lane >> 2, t = lane & 3;

    const __half* kb = g_kh + (size_t)(b * H_ + h) * S_ * D_;
    const __half* vb = g_vh + (size_t)(b * H_ + h) * S_ * D_;

    // prologue: prefetch K chunk 0 (64 x 128 halfs)
#pragma unroll
    for (int l = 0; l < 4; l++) {
        int idx = tid + l * 256;
        int r = idx >> 4, c = (idx & 15) * 8;
        CP16(s2u(&sK[r * KPH + c]), &kb[(size_t)r * D_ + c]);
    }
    CP_COMMIT();

    // stage Q tile (fp16, already scaled)
#pragma unroll
    for (int l = 0; l < 8; l++) {
        int idx = tid + l * 256;
        int r = idx >> 4, c = (idx & 15) * 8;
        uint4 qv = *(const uint4*)&g_qh[(size_t)(b * T_ + qt * 128 + r) * E_ + h * D_ + c];
        *(uint4*)&sQ[r * QPH + c] = qv;
    }

    float m0 = -1e30f, m1 = -1e30f, l0 = 0.f, l1 = 0.f;
    float acc_o[16][4];
#pragma unroll
    for (int nj = 0; nj < 16; nj++)
#pragma unroll
        for (int q = 0; q < 4; q++) acc_o[nj][q] = 0.f;

    for (int ci = 0; ci < S_ / 64; ci++) {
        const int cur = ci & 1;
        const __half* cK = sK + cur * 64 * KPH;

        CP_WAIT0();
        __syncthreads();

        // prefetch V_ci, then K_{ci+1}
        {
            const size_t vbase = (size_t)(ci * 64) * D_;
#pragma unroll
            for (int l = 0; l < 4; l++) {
                int idx = tid + l * 256;
                int r = idx >> 4, c = (idx & 15) * 8;
                CP16(s2u(&sV[r * VPH + c]), &vb[vbase + (size_t)r * D_ + c]);
            }
            CP_COMMIT();
        }
        if (ci + 1 < S_ / 64) {
            const size_t kbase = (size_t)((ci + 1) * 64) * D_;
            __half* nK = sK + (cur ^ 1) * 64 * KPH;
#pragma unroll
            for (int l = 0; l < 4; l++) {
                int idx = tid + l * 256;
                int r = idx >> 4, c = (idx & 15) * 8;
                CP16(s2u(&nK[r * KPH + c]), &kb[kbase + (size_t)r * D_ + c]);
            }
            CP_COMMIT();
        }

        // S = Q K^T   (warp: 16 q-rows x 64 keys, 8 k-steps)
        float accs[8][4];
#pragma unroll
        for (int nj = 0; nj < 8; nj++)
#pragma unroll
            for (int q = 0; q < 4; q++) accs[nj][q] = 0.f;

#pragma unroll
        for (int ks = 0; ks < 8; ks++) {
            int r = w * 16 + g;
            unsigned a0 = *(const unsigned*)&sQ[r * QPH + ks * 16 + 2 * t];
            unsigned a1 = *(const unsigned*)&sQ[(r + 8) * QPH + ks * 16 + 2 * t];
            unsigned a2 = *(const unsigned*)&sQ[r * QPH + ks * 16 + 2 * t + 8];
            unsigned a3 = *(const unsigned*)&sQ[(r + 8) * QPH + ks * 16 + 2 * t + 8];
#pragma unroll
            for (int nj = 0; nj < 8; nj++) {
                unsigned b0 = *(const unsigned*)&cK[(nj * 8 + g) * KPH + ks * 16 + 2 * t];
                unsigned b1 = *(const unsigned*)&cK[(nj * 8 + g) * KPH + ks * 16 + 2 * t + 8];
                mma_f16(accs[nj], a0, a1, a2, a3, b0, b1);
            }
        }

        // online softmax
        float rm0 = -1e30f, rm1 = -1e30f;
#pragma unroll
        for (int nj = 0; nj < 8; nj++) {
            rm0 = fmaxf(rm0, fmaxf(accs[nj][0], accs[nj][1]));
            rm1 = fmaxf(rm1, fmaxf(accs[nj][2], accs[nj][3]));
        }
        rm0 = fmaxf(rm0, __shfl_xor_sync(0xffffffffu, rm0, 1));
        rm0 = fmaxf(rm0, __shfl_xor_sync(0xffffffffu, rm0, 2));
        rm1 = fmaxf(rm1, __shfl_xor_sync(0xffffffffu, rm1, 1));
        rm1 = fmaxf(rm1, __shfl_xor_sync(0xffffffffu, rm1, 2));

        float nm0 = fmaxf(m0, rm0), nm1 = fmaxf(m1, rm1);
        float al0 = __expf(m0 - nm0), al1 = __expf(m1 - nm1);
        m0 = nm0; m1 = nm1;

        float sum0 = 0.f, sum1 = 0.f;
        int r0 = w * 16 + g;
#pragma unroll
        for (int nj = 0; nj < 8; nj++) {
            float p0 = __expf(accs[nj][0] - nm0);
            float p1 = __expf(accs[nj][1] - nm0);
            float p2 = __expf(accs[nj][2] - nm1);
            float p3 = __expf(accs[nj][3] - nm1);
            sum0 += p0 + p1;
            sum1 += p2 + p3;
            int c = nj * 8 + 2 * t;
            *(unsigned*)&sP[r0 * PPH + c]       = h2u(p0, p1);
            *(unsigned*)&sP[(r0 + 8) * PPH + c] = h2u(p2, p3);
        }
        sum0 += __shfl_xor_sync(0xffffffffu, sum0, 1);
        sum0 += __shfl_xor_sync(0xffffffffu, sum0, 2);
        sum1 += __shfl_xor_sync(0xffffffffu, sum1, 1);
        sum1 += __shfl_xor_sync(0xffffffffu, sum1, 2);
        l0 = l0 * al0 + sum0;
        l1 = l1 * al1 + sum1;

#pragma unroll
        for (int nj = 0; nj < 16; nj++) {
            acc_o[nj][0] *= al0; acc_o[nj][1] *= al0;
            acc_o[nj][2] *= al1; acc_o[nj][3] *= al1;
        }

        if (ci + 1 < S_ / 64) { CP_WAIT1(); } else { CP_WAIT0(); }
        __syncthreads();

        // O += P V   (V b-frags via ldmatrix.trans on row-major sV)
#pragma unroll
        for (int ks = 0; ks < 4; ks++) {
            unsigned a0 = *(const unsigned*)&sP[(w * 16 + g) * PPH + ks * 16 + 2 * t];
            unsigned a1 = *(const unsigned*)&sP[(w * 16 + g + 8) * PPH + ks * 16 + 2 * t];
            unsigned a2 = *(const unsigned*)&sP[(w * 16 + g) * PPH + ks * 16 + 2 * t + 8];
            unsigned a3 = *(const unsigned*)&sP[(w * 16 + g + 8) * PPH + ks * 16 + 2 * t + 8];
            int key = ks * 16 + (lane & 15);
#pragma unroll
            for (int nj2 = 0; nj2 < 8; nj2++) {
                int dd = nj2 * 16 + (lane >> 4) * 8;
                unsigned bb[4];
                ldm_x4_trans(bb, s2u(&sV[key * VPH + dd]));
                mma_f16(acc_o[nj2 * 2],     a0, a1, a2, a3, bb[0], bb[1]);
                mma_f16(acc_o[nj2 * 2 + 1], a0, a1, a2, a3, bb[2], bb[3]);
            }
        }
    }

    // epilogue: normalize, write fp16 to g_ah
    float inv0 = 1.f / l0, inv1 = 1.f / l1;
    int row = b * T_ + qt * 128 + w * 16 + g;
#pragma unroll
    for (int nj = 0; nj < 16; nj++) {
        int col = h * D_ + nj * 8 + 2 * t;
        *(unsigned*)&g_ah[(size_t)row * E_ + col] =
            h2u(acc_o[nj][0] * inv0, acc_o[nj][1] * inv0);
        *(unsigned*)&g_ah[(size_t)(row + 8) * E_ + col] =
            h2u(acc_o[nj][2] * inv1, acc_o[nj][3] * inv1);
    }
}

// ---------------------------------------------------------------------------
extern "C" void kernel_launch(void* const* d_in, const int* in_sizes, int n_in,
                              void* d_out, int out_size)
{
    const float* x      = (const float*)d_in[0];
    const float* past_k = (const float*)d_in[1];
    const float* past_v = (const float*)d_in[2];
    const float* Wq     = (const float*)d_in[3];
    const float* bq     = (const float*)d_in[4];
    const float* Wk     = (const float*)d_in[5];
    const float* bk     = (const float*)d_in[6];
    const float* Wv     = (const float*)d_in[7];
    const float* bv     = (const float*)d_in[8];
    const float* Wo     = (const float*)d_in[9];
    const float* bo     = (const float*)d_in[10];

    float* out = (float*)d_out;                       // [B,T,E]
    float* kc  = out + (size_t)NTOK * E_;             // [B,H,S,D]
    float* vc  = kc + (size_t)CACHE_ELEMS;            // [B,H,S,D]

    // fp32 -> fp16 conversions (single launch)
    to_half_all<<<dim3(512, 5), 256>>>(x, Wq, Wk, Wv, Wo);

    cudaFuncSetAttribute(gemm_h, cudaFuncAttributeMaxDynamicSharedMemorySize, GEMM_SMEM);
    cudaFuncSetAttribute(attn_h, cudaFuncAttributeMaxDynamicSharedMemorySize, ATTN_SMEM);

    // fused QKV projections (z=0..2) + past-KV copy (z=3) in one launch
    dim3 gq(E_ / 128, NTOK / 128, 4);
    gemm_h<<<gq, 256, GEMM_SMEM>>>(0, bq, bk, bv, bo, past_k, past_v,
                                   kc, vc, out);

    // attention
    attn_h<<<dim3(T_ / 128, H_, B_), 256, ATTN_SMEM>>>();

    // output projection (mode 4)
    dim3 go(E_ / 128, NTOK / 128, 1);
    gemm_h<<<go, 256, GEMM_SMEM>>>(4, bq, bk, bv, bo, past_k, past_v,
                                   kc, vc, out);
}

// round 9
// speedup vs baseline: 3.7175x; 1.0890x over previous
#include <cuda_runtime.h>
#include <cuda_fp16.h>
#include <math.h>
#include <stdint.h>

// Problem constants
#define E_   2048
#define H_   16
#define D_   128
#define B_   4
#define T_   1024
#define TP_  3072
#define S_   (TP_ + T_)      // 4096
#define NTOK (B_ * T_)       // 4096
#define CACHE_ELEMS (B_ * H_ * S_ * D_)   // 33.5M
#define QSCALE 0.08838834764831845f       // 1/sqrt(128)

// Scratch (device globals -- no allocations allowed)
__device__ __half g_xh[NTOK * E_];     // x in fp16
__device__ __half g_wqh[E_ * E_];
__device__ __half g_wkh[E_ * E_];
__device__ __half g_wvh[E_ * E_];
__device__ __half g_woh[E_ * E_];
__device__ __half g_qh[NTOK * E_];     // Q (scaled) fp16
__device__ __half g_ah[NTOK * E_];     // attention output fp16
__device__ __half g_kh[CACHE_ELEMS];   // K cache shadow fp16 [b,h,s,d]
__device__ __half g_vh[CACHE_ELEMS];   // V cache shadow fp16 [b,h,s,d]

// ---------------------------------------------------------------------------
// Helpers
// ---------------------------------------------------------------------------
__device__ __forceinline__ void mma_f16(float c[4],
    unsigned a0, unsigned a1, unsigned a2, unsigned a3,
    unsigned b0, unsigned b1)
{
    asm volatile(
        "mma.sync.aligned.m16n8k16.row.col.f32.f16.f16.f32 "
        "{%0,%1,%2,%3}, {%4,%5,%6,%7}, {%8,%9}, {%0,%1,%2,%3};"
        : "+f"(c[0]), "+f"(c[1]), "+f"(c[2]), "+f"(c[3])
        : "r"(a0), "r"(a1), "r"(a2), "r"(a3), "r"(b0), "r"(b1));
}

__device__ __forceinline__ unsigned s2u(const void* p) {
    return (unsigned)__cvta_generic_to_shared(p);
}

__device__ __forceinline__ unsigned h2u(float x, float y) {
    __half2 h = __floats2half2_rn(x, y);
    return *(unsigned*)&h;
}

#define CP16(dst_u32, src_ptr) \
    asm volatile("cp.async.cg.shared.global [%0], [%1], 16;" :: "r"(dst_u32), "l"(src_ptr))
#define CP_COMMIT() asm volatile("cp.async.commit_group;")
#define CP_WAIT0()  asm volatile("cp.async.wait_group 0;")
#define CP_WAIT1()  asm volatile("cp.async.wait_group 1;")

__device__ __forceinline__ void ldm_x4(unsigned r[4], unsigned addr) {
    asm volatile(
        "ldmatrix.sync.aligned.m8n8.x4.shared.b16 {%0,%1,%2,%3}, [%4];"
        : "=r"(r[0]), "=r"(r[1]), "=r"(r[2]), "=r"(r[3]) : "r"(addr));
}

__device__ __forceinline__ void ldm_x4_trans(unsigned r[4], unsigned addr) {
    asm volatile(
        "ldmatrix.sync.aligned.m8n8.x4.trans.shared.b16 {%0,%1,%2,%3}, [%4];"
        : "=r"(r[0]), "=r"(r[1]), "=r"(r[2]), "=r"(r[3]) : "r"(addr));
}

// ---------------------------------------------------------------------------
// Fused fp32 -> fp16 conversion (x + 4 weights in one launch)
// blockIdx.y: 0=x, 1=Wq, 2=Wk, 3=Wv, 4=Wo
// ---------------------------------------------------------------------------
__global__ void to_half_all(const float* __restrict__ x,
                            const float* __restrict__ wq,
                            const float* __restrict__ wk,
                            const float* __restrict__ wv,
                            const float* __restrict__ wo)
{
    const int z = blockIdx.y;
    const float* src = (z == 0) ? x : (z == 1) ? wq : (z == 2) ? wk
                      : (z == 3) ? wv : wo;
    __half* dst = (z == 0) ? g_xh : (z == 1) ? g_wqh : (z == 2) ? g_wkh
                 : (z == 3) ? g_wvh : g_woh;
    const int n4 = (z == 0) ? NTOK * E_ / 4 : E_ * E_ / 4;
    for (int i = blockIdx.x * blockDim.x + threadIdx.x; i < n4;
         i += gridDim.x * blockDim.x) {
        float4 v = ((const float4*)src)[i];
        uint2 u = { h2u(v.x, v.y), h2u(v.z, v.w) };
        ((uint2*)dst)[i] = u;
    }
}

// ---------------------------------------------------------------------------
// fp16 tensor-core GEMM + fused past-KV copy. All fragment loads via ldmatrix.
// mode = base_mode + blockIdx.z:
//   0=Q-proj, 1=K-proj, 2=V-proj, 3=past-KV copy, 4=O-proj.
// Block 128x128, BK=64 halfs, 8 warps (4x2), 2-stage cp.async pipeline.
// ---------------------------------------------------------------------------
#define GAP 72
#define HA  (128 * GAP)         // halfs per buffer (9216)
#define GEMM_SMEM (4 * HA * 2)  // 73728 bytes

__global__ __launch_bounds__(256, 2) void gemm_h(
    int base_mode,
    const float* __restrict__ bq, const float* __restrict__ bk,
    const float* __restrict__ bv, const float* __restrict__ bo,
    const float* __restrict__ past_k, const float* __restrict__ past_v,
    float* __restrict__ kc, float* __restrict__ vc, float* __restrict__ outp)
{
    const int mode = base_mode + blockIdx.z;

    if (mode == 3) {
        // ---- past copy CTAs (grid-stride over float4s) ----
        const int total4 = B_ * H_ * TP_ * D_ / 4;
        const int nct = gridDim.x * gridDim.y;        // 512
        const int cta = blockIdx.y * gridDim.x + blockIdx.x;
        for (int idx = cta * 256 + threadIdx.x; idx < total4; idx += nct * 256) {
            int bh  = idx / (TP_ * D_ / 4);
            int off = (idx % (TP_ * D_ / 4)) * 4;
            size_t dst = (size_t)bh * S_ * D_ + off;
            float4 kv = *(const float4*)&past_k[(size_t)idx * 4];
            float4 vv = *(const float4*)&past_v[(size_t)idx * 4];
            *(float4*)&kc[dst] = kv;
            *(float4*)&vc[dst] = vv;
            uint2 kh = { h2u(kv.x, kv.y), h2u(kv.z, kv.w) };
            uint2 vh = { h2u(vv.x, vv.y), h2u(vv.z, vv.w) };
            *(uint2*)&g_kh[dst] = kh;
            *(uint2*)&g_vh[dst] = vh;
        }
        return;
    }

    extern __shared__ __half sh[];
    __half* bufA[2] = { sh,      sh + 2 * HA };
    __half* bufB[2] = { sh + HA, sh + 3 * HA };

    const __half* A    = (mode < 3) ? g_xh : g_ah;
    const __half* W    = (mode == 0) ? g_wqh : (mode == 1) ? g_wkh
                        : (mode == 2) ? g_wvh : g_woh;
    const float* bias  = (mode == 0) ? bq : (mode == 1) ? bk
                        : (mode == 2) ? bv : bo;

    const int tid  = threadIdx.x;
    const int lane = tid & 31, wid = tid >> 5;
    const int wm = wid >> 1, wn = wid & 1;
    const int g = lane >> 2, t = lane & 3;
    const int brow = blockIdx.y * 128, bcol = blockIdx.x * 128;

    // ldmatrix per-lane source row/col offset (halfs):
    // lanes 0..15 -> rows 0..15, lanes 16..31 -> same rows, col +8
    const unsigned lmo = (((lane & 15) * GAP) + (lane >> 4) * 8) * 2;  // bytes

    float acc[2][8][4];
#pragma unroll
    for (int mi = 0; mi < 2; mi++)
#pragma unroll
        for (int nj = 0; nj < 8; nj++)
#pragma unroll
            for (int q = 0; q < 4; q++) acc[mi][nj][q] = 0.f;

    // prologue: buffer 0 (k0 = 0)
#pragma unroll
    for (int l = 0; l < 4; l++) {
        int idx = tid + l * 256;
        int r = idx >> 3, c = (idx & 7) * 8;
        CP16(s2u(&bufA[0][r * GAP + c]), &A[(size_t)(brow + r) * E_ + c]);
        CP16(s2u(&bufB[0][r * GAP + c]), &W[(size_t)(bcol + r) * E_ + c]);
    }
    CP_COMMIT();

    const int KT = E_ / 64;  // 32
    for (int kt = 0; kt < KT; kt++) {
        const int cur = kt & 1;
        CP_WAIT0();
        __syncthreads();
        if (kt + 1 < KT) {
            const int k0 = (kt + 1) * 64;
#pragma unroll
            for (int l = 0; l < 4; l++) {
                int idx = tid + l * 256;
                int r = idx >> 3, c = (idx & 7) * 8;
                CP16(s2u(&bufA[cur ^ 1][r * GAP + c]), &A[(size_t)(brow + r) * E_ + k0 + c]);
                CP16(s2u(&bufB[cur ^ 1][r * GAP + c]), &W[(size_t)(bcol + r) * E_ + k0 + c]);
            }
            CP_COMMIT();
        }

        const unsigned aBase = s2u(bufA[cur]) + (unsigned)(wm * 32 * GAP * 2) + lmo;
        const unsigned bBase = s2u(bufB[cur]) + (unsigned)(wn * 64 * GAP * 2) + lmo;

#pragma unroll
        for (int ks = 0; ks < 4; ks++) {
            const unsigned koff = ks * 32;    // 16 halfs = 32 bytes
            unsigned a[2][4];
            ldm_x4(a[0], aBase + koff);
            ldm_x4(a[1], aBase + 16 * GAP * 2 + koff);
#pragma unroll
            for (int njp = 0; njp < 4; njp++) {
                unsigned bfr[4];
                ldm_x4(bfr, bBase + njp * 16 * GAP * 2 + koff);
                mma_f16(acc[0][2 * njp],     a[0][0], a[0][1], a[0][2], a[0][3], bfr[0], bfr[2]);
                mma_f16(acc[0][2 * njp + 1], a[0][0], a[0][1], a[0][2], a[0][3], bfr[1], bfr[3]);
                mma_f16(acc[1][2 * njp],     a[1][0], a[1][1], a[1][2], a[1][3], bfr[0], bfr[2]);
                mma_f16(acc[1][2 * njp + 1], a[1][0], a[1][1], a[1][2], a[1][3], bfr[1], bfr[3]);
            }
        }
    }
    __syncthreads();

    // epilogue
#pragma unroll
    for (int mi = 0; mi < 2; mi++) {
#pragma unroll
        for (int nj = 0; nj < 8; nj++) {
            int row = brow + wm * 32 + mi * 16 + g;
            int col = bcol + wn * 64 + nj * 8 + 2 * t;
            float b0 = bias[col], b1 = bias[col + 1];
            float v00 = acc[mi][nj][0] + b0, v01 = acc[mi][nj][1] + b1;
            float v10 = acc[mi][nj][2] + b0, v11 = acc[mi][nj][3] + b1;
            if (mode == 0) {
                *(unsigned*)&g_qh[(size_t)row * E_ + col] =
                    h2u(v00 * QSCALE, v01 * QSCALE);
                *(unsigned*)&g_qh[(size_t)(row + 8) * E_ + col] =
                    h2u(v10 * QSCALE, v11 * QSCALE);
            } else if (mode == 4) {
                float2 f0 = { v00, v01 }, f1 = { v10, v11 };
                *(float2*)&outp[(size_t)row * E_ + col]       = f0;
                *(float2*)&outp[(size_t)(row + 8) * E_ + col] = f1;
            } else {
                float* dst   = (mode == 1) ? kc  : vc;
                __half* dstH = (mode == 1) ? g_kh : g_vh;
                int b_i = row >> 10, t_i = row & 1023;
                int h_i = col >> 7,  d_i = col & 127;
                size_t base = ((size_t)(b_i * H_ + h_i) * S_ + TP_ + t_i) * D_ + d_i;
                float2 f0 = { v00, v01 }, f1 = { v10, v11 };
                *(float2*)&dst[base]             = f0;
                *(float2*)&dst[base + 8ull * D_] = f1;
                *(unsigned*)&dstH[base]             = h2u(v00, v01);
                *(unsigned*)&dstH[base + 8ull * D_] = h2u(v10, v11);
            }
        }
    }
}

// ---------------------------------------------------------------------------
// fp16 tensor-core flash attention; all fragments via ldmatrix.
// CTA = (qtile 128, h, b). 256 thr, 8 warps; warp w owns rows [w*16, +16).
// 2 CTAs/SM. K double-buffered via cp.async; V prefetched during QK.
// ---------------------------------------------------------------------------
#define QPH 136
#define KPH 136
#define VPH 136
#define PPH 72
#define ATTN_SMEM ((128*QPH + 2*64*KPH + 64*VPH + 128*PPH) * 2)

__global__ __launch_bounds__(256, 2) void attn_h(void)
{
    extern __shared__ __half sm[];
    __half* sQ = sm;                         // 128 x 136
    __half* sK = sQ + 128 * QPH;             // 2 x 64 x 136
    __half* sV = sK + 2 * 64 * KPH;          // 64 x 136
    __half* sP = sV + 64 * VPH;              // 128 x 72

    const int qt = blockIdx.x, h = blockIdx.y, b = blockIdx.z;
    const int tid = threadIdx.x, lane = tid & 31, w = tid >> 5;
    const int g = lane >> 2, t = lane & 3;

    const __half* kb = g_kh + (size_t)(b * H_ + h) * S_ * D_;
    const __half* vb = g_vh + (size_t)(b * H_ + h) * S_ * D_;

    // prologue: prefetch K chunk 0 (64 x 128 halfs)
#pragma unroll
    for (int l = 0; l < 4; l++) {
        int idx = tid + l * 256;
        int r = idx >> 4, c = (idx & 15) * 8;
        CP16(s2u(&sK[r * KPH + c]), &kb[(size_t)r * D_ + c]);
    }
    CP_COMMIT();

    // stage Q tile (fp16, already scaled)
#pragma unroll
    for (int l = 0; l < 8; l++) {
        int idx = tid + l * 256;
        int r = idx >> 4, c = (idx & 15) * 8;
        uint4 qv = *(const uint4*)&g_qh[(size_t)(b * T_ + qt * 128 + r) * E_ + h * D_ + c];
        *(uint4*)&sQ[r * QPH + c] = qv;
    }

    float m0 = -1e30f, m1 = -1e30f, l0 = 0.f, l1 = 0.f;
    float acc_o[16][4];
#pragma unroll
    for (int nj = 0; nj < 16; nj++)
#pragma unroll
        for (int q = 0; q < 4; q++) acc_o[nj][q] = 0.f;

    // ldmatrix per-lane offsets (bytes)
    const unsigned lmoQ = (((lane & 15) * QPH) + (lane >> 4) * 8) * 2;
    const unsigned lmoK = (((lane & 15) * KPH) + (lane >> 4) * 8) * 2;
    const unsigned lmoP = (((lane & 15) * PPH) + (lane >> 4) * 8) * 2;
    const unsigned aQBase = s2u(sQ) + (unsigned)(w * 16 * QPH * 2) + lmoQ;
    const unsigned aPBase = s2u(sP) + (unsigned)(w * 16 * PPH * 2) + lmoP;

    for (int ci = 0; ci < S_ / 64; ci++) {
        const int cur = ci & 1;
        const unsigned bKBase = s2u(sK + cur * 64 * KPH) + lmoK;

        CP_WAIT0();
        __syncthreads();

        // prefetch V_ci, then K_{ci+1}
        {
            const size_t vbase = (size_t)(ci * 64) * D_;
#pragma unroll
            for (int l = 0; l < 4; l++) {
                int idx = tid + l * 256;
                int r = idx >> 4, c = (idx & 15) * 8;
                CP16(s2u(&sV[r * VPH + c]), &vb[vbase + (size_t)r * D_ + c]);
            }
            CP_COMMIT();
        }
        if (ci + 1 < S_ / 64) {
            const size_t kbase = (size_t)((ci + 1) * 64) * D_;
            __half* nK = sK + (cur ^ 1) * 64 * KPH;
#pragma unroll
            for (int l = 0; l < 4; l++) {
                int idx = tid + l * 256;
                int r = idx >> 4, c = (idx & 15) * 8;
                CP16(s2u(&nK[r * KPH + c]), &kb[kbase + (size_t)r * D_ + c]);
            }
            CP_COMMIT();
        }

        // S = Q K^T   (warp: 16 q-rows x 64 keys, 8 k-steps)
        float accs[8][4];
#pragma unroll
        for (int nj = 0; nj < 8; nj++)
#pragma unroll
            for (int q = 0; q < 4; q++) accs[nj][q] = 0.f;

#pragma unroll
        for (int ks = 0; ks < 8; ks++) {
            const unsigned koff = ks * 32;
            unsigned a[4];
            ldm_x4(a, aQBase + koff);
#pragma unroll
            for (int njp = 0; njp < 4; njp++) {
                unsigned bfr[4];
                ldm_x4(bfr, bKBase + njp * 16 * KPH * 2 + koff);
                mma_f16(accs[2 * njp],     a[0], a[1], a[2], a[3], bfr[0], bfr[2]);
                mma_f16(accs[2 * njp + 1], a[0], a[1], a[2], a[3], bfr[1], bfr[3]);
            }
        }

        // online softmax
        float rm0 = -1e30f, rm1 = -1e30f;
#pragma unroll
        for (int nj = 0; nj < 8; nj++) {
            rm0 = fmaxf(rm0, fmaxf(accs[nj][0], accs[nj][1]));
            rm1 = fmaxf(rm1, fmaxf(accs[nj][2], accs[nj][3]));
        }
        rm0 = fmaxf(rm0, __shfl_xor_sync(0xffffffffu, rm0, 1));
        rm0 = fmaxf(rm0, __shfl_xor_sync(0xffffffffu, rm0, 2));
        rm1 = fmaxf(rm1, __shfl_xor_sync(0xffffffffu, rm1, 1));
        rm1 = fmaxf(rm1, __shfl_xor_sync(0xffffffffu, rm1, 2));

        float nm0 = fmaxf(m0, rm0), nm1 = fmaxf(m1, rm1);
        float al0 = __expf(m0 - nm0), al1 = __expf(m1 - nm1);
        m0 = nm0; m1 = nm1;

        float sum0 = 0.f, sum1 = 0.f;
        int r0 = w * 16 + g;
#pragma unroll
        for (int nj = 0; nj < 8; nj++) {
            float p0 = __expf(accs[nj][0] - nm0);
            float p1 = __expf(accs[nj][1] - nm0);
            float p2 = __expf(accs[nj][2] - nm1);
            float p3 = __expf(accs[nj][3] - nm1);
            sum0 += p0 + p1;
            sum1 += p2 + p3;
            int c = nj * 8 + 2 * t;
            *(unsigned*)&sP[r0 * PPH + c]       = h2u(p0, p1);
            *(unsigned*)&sP[(r0 + 8) * PPH + c] = h2u(p2, p3);
        }
        sum0 += __shfl_xor_sync(0xffffffffu, sum0, 1);
        sum0 += __shfl_xor_sync(0xffffffffu, sum0, 2);
        sum1 += __shfl_xor_sync(0xffffffffu, sum1, 1);
        sum1 += __shfl_xor_sync(0xffffffffu, sum1, 2);
        l0 = l0 * al0 + sum0;
        l1 = l1 * al1 + sum1;

#pragma unroll
        for (int nj = 0; nj < 16; nj++) {
            acc_o[nj][0] *= al0; acc_o[nj][1] *= al0;
            acc_o[nj][2] *= al1; acc_o[nj][3] *= al1;
        }

        if (ci + 1 < S_ / 64) { CP_WAIT1(); } else { CP_WAIT0(); }
        __syncthreads();

        // O += P V   (P a-frags via ldmatrix; V b-frags via ldmatrix.trans)
#pragma unroll
        for (int ks = 0; ks < 4; ks++) {
            unsigned a[4];
            ldm_x4(a, aPBase + ks * 32);
            int key = ks * 16 + (lane & 15);
#pragma unroll
            for (int nj2 = 0; nj2 < 8; nj2++) {
                int dd = nj2 * 16 + (lane >> 4) * 8;
                unsigned bb[4];
                ldm_x4_trans(bb, s2u(&sV[key * VPH + dd]));
                mma_f16(acc_o[nj2 * 2],     a[0], a[1], a[2], a[3], bb[0], bb[1]);
                mma_f16(acc_o[nj2 * 2 + 1], a[0], a[1], a[2], a[3], bb[2], bb[3]);
            }
        }
    }

    // epilogue: normalize, write fp16 to g_ah
    float inv0 = 1.f / l0, inv1 = 1.f / l1;
    int row = b * T_ + qt * 128 + w * 16 + g;
#pragma unroll
    for (int nj = 0; nj < 16; nj++) {
        int col = h * D_ + nj * 8 + 2 * t;
        *(unsigned*)&g_ah[(size_t)row * E_ + col] =
            h2u(acc_o[nj][0] * inv0, acc_o[nj][1] * inv0);
        *(unsigned*)&g_ah[(size_t)(row + 8) * E_ + col] =
            h2u(acc_o[nj][2] * inv1, acc_o[nj][3] * inv1);
    }
}

// ---------------------------------------------------------------------------
extern "C" void kernel_launch(void* const* d_in, const int* in_sizes, int n_in,
                              void* d_out, int out_size)
{
    const float* x      = (const float*)d_in[0];
    const float* past_k = (const float*)d_in[1];
    const float* past_v = (const float*)d_in[2];
    const float* Wq     = (const float*)d_in[3];
    const float* bq     = (const float*)d_in[4];
    const float* Wk     = (const float*)d_in[5];
    const float* bk     = (const float*)d_in[6];
    const float* Wv     = (const float*)d_in[7];
    const float* bv     = (const float*)d_in[8];
    const float* Wo     = (const float*)d_in[9];
    const float* bo     = (const float*)d_in[10];

    float* out = (float*)d_out;                       // [B,T,E]
    float* kc  = out + (size_t)NTOK * E_;             // [B,H,S,D]
    float* vc  = kc + (size_t)CACHE_ELEMS;            // [B,H,S,D]

    // fp32 -> fp16 conversions (single launch)
    to_half_all<<<dim3(512, 5), 256>>>(x, Wq, Wk, Wv, Wo);

    cudaFuncSetAttribute(gemm_h, cudaFuncAttributeMaxDynamicSharedMemorySize, GEMM_SMEM);
    cudaFuncSetAttribute(attn_h, cudaFuncAttributeMaxDynamicSharedMemorySize, ATTN_SMEM);

    // fused QKV projections (z=0..2) + past-KV copy (z=3) in one launch
    dim3 gq(E_ / 128, NTOK / 128, 4);
    gemm_h<<<gq, 256, GEMM_SMEM>>>(0, bq, bk, bv, bo, past_k, past_v,
                                   kc, vc, out);

    // attention
    attn_h<<<dim3(T_ / 128, H_, B_), 256, ATTN_SMEM>>>();

    // output projection (mode 4)
    dim3 go(E_ / 128, NTOK / 128, 1);
    gemm_h<<<go, 256, GEMM_SMEM>>>(4, bq, bk, bv, bo, past_k, past_v,
                                   kc, vc, out);
}

// round 10
// speedup vs baseline: 3.7764x; 1.0158x over previous
#include <cuda_runtime.h>
#include <cuda_fp16.h>
#include <math.h>
#include <stdint.h>

// Problem constants
#define E_   2048
#define H_   16
#define D_   128
#define B_   4
#define T_   1024
#define TP_  3072
#define S_   (TP_ + T_)      // 4096
#define NTOK (B_ * T_)       // 4096
#define CACHE_ELEMS (B_ * H_ * S_ * D_)   // 33.5M
#define QSCALE 0.08838834764831845f       // 1/sqrt(128)

// Scratch (device globals -- no allocations allowed)
__device__ __half g_xh[NTOK * E_];     // x in fp16
__device__ __half g_wqh[E_ * E_];
__device__ __half g_wkh[E_ * E_];
__device__ __half g_wvh[E_ * E_];
__device__ __half g_woh[E_ * E_];
__device__ __half g_qh[NTOK * E_];     // Q (scaled) fp16
__device__ __half g_ah[NTOK * E_];     // attention output fp16
__device__ __half g_kh[CACHE_ELEMS];   // K cache shadow fp16 [b,h,s,d]
__device__ __half g_vh[CACHE_ELEMS];   // V cache shadow fp16 [b,h,s,d]

// ---------------------------------------------------------------------------
// Helpers
// ---------------------------------------------------------------------------
__device__ __forceinline__ void mma_f16(float c[4],
    unsigned a0, unsigned a1, unsigned a2, unsigned a3,
    unsigned b0, unsigned b1)
{
    asm volatile(
        "mma.sync.aligned.m16n8k16.row.col.f32.f16.f16.f32 "
        "{%0,%1,%2,%3}, {%4,%5,%6,%7}, {%8,%9}, {%0,%1,%2,%3};"
        : "+f"(c[0]), "+f"(c[1]), "+f"(c[2]), "+f"(c[3])
        : "r"(a0), "r"(a1), "r"(a2), "r"(a3), "r"(b0), "r"(b1));
}

__device__ __forceinline__ unsigned s2u(const void* p) {
    return (unsigned)__cvta_generic_to_shared(p);
}

__device__ __forceinline__ unsigned h2u(float x, float y) {
    __half2 h = __floats2half2_rn(x, y);
    return *(unsigned*)&h;
}

#define CP16(dst_u32, src_ptr) \
    asm volatile("cp.async.cg.shared.global [%0], [%1], 16;" :: "r"(dst_u32), "l"(src_ptr))
#define CP_COMMIT() asm volatile("cp.async.commit_group;")
#define CP_WAIT0()  asm volatile("cp.async.wait_group 0;")
#define CP_WAIT1()  asm volatile("cp.async.wait_group 1;")

__device__ __forceinline__ void ldm_x4(unsigned r[4], unsigned addr) {
    asm volatile(
        "ldmatrix.sync.aligned.m8n8.x4.shared.b16 {%0,%1,%2,%3}, [%4];"
        : "=r"(r[0]), "=r"(r[1]), "=r"(r[2]), "=r"(r[3]) : "r"(addr));
}

__device__ __forceinline__ void ldm_x4_trans(unsigned r[4], unsigned addr) {
    asm volatile(
        "ldmatrix.sync.aligned.m8n8.x4.trans.shared.b16 {%0,%1,%2,%3}, [%4];"
        : "=r"(r[0]), "=r"(r[1]), "=r"(r[2]), "=r"(r[3]) : "r"(addr));
}

// ---------------------------------------------------------------------------
// Fused fp32 -> fp16 conversion (x + 4 weights in one launch)
// ---------------------------------------------------------------------------
__global__ void to_half_all(const float* __restrict__ x,
                            const float* __restrict__ wq,
                            const float* __restrict__ wk,
                            const float* __restrict__ wv,
                            const float* __restrict__ wo)
{
    const int z = blockIdx.y;
    const float* src = (z == 0) ? x : (z == 1) ? wq : (z == 2) ? wk
                      : (z == 3) ? wv : wo;
    __half* dst = (z == 0) ? g_xh : (z == 1) ? g_wqh : (z == 2) ? g_wkh
                 : (z == 3) ? g_wvh : g_woh;
    const int n4 = (z == 0) ? NTOK * E_ / 4 : E_ * E_ / 4;
    for (int i = blockIdx.x * blockDim.x + threadIdx.x; i < n4;
         i += gridDim.x * blockDim.x) {
        float4 v = ((const float4*)src)[i];
        uint2 u = { h2u(v.x, v.y), h2u(v.z, v.w) };
        ((uint2*)dst)[i] = u;
    }
}

// ---------------------------------------------------------------------------
// fp16 tensor-core GEMM + fused past-KV copy. Register-pipelined ldmatrix.
// mode = base_mode + blockIdx.z:
//   0=Q-proj, 1=K-proj, 2=V-proj, 3=past-KV copy, 4=O-proj.
// ---------------------------------------------------------------------------
#define GAP 72
#define HA  (128 * GAP)         // halfs per buffer (9216)
#define GEMM_SMEM (4 * HA * 2)  // 73728 bytes

__global__ __launch_bounds__(256, 2) void gemm_h(
    int base_mode,
    const float* __restrict__ bq, const float* __restrict__ bk,
    const float* __restrict__ bv, const float* __restrict__ bo,
    const float* __restrict__ past_k, const float* __restrict__ past_v,
    float* __restrict__ kc, float* __restrict__ vc, float* __restrict__ outp)
{
    const int mode = base_mode + blockIdx.z;

    if (mode == 3) {
        // ---- past copy CTAs (grid-stride over float4s) ----
        const int total4 = B_ * H_ * TP_ * D_ / 4;
        const int nct = gridDim.x * gridDim.y;
        const int cta = blockIdx.y * gridDim.x + blockIdx.x;
        for (int idx = cta * 256 + threadIdx.x; idx < total4; idx += nct * 256) {
            int bh  = idx / (TP_ * D_ / 4);
            int off = (idx % (TP_ * D_ / 4)) * 4;
            size_t dst = (size_t)bh * S_ * D_ + off;
            float4 kv = *(const float4*)&past_k[(size_t)idx * 4];
            float4 vv = *(const float4*)&past_v[(size_t)idx * 4];
            *(float4*)&kc[dst] = kv;
            *(float4*)&vc[dst] = vv;
            uint2 kh = { h2u(kv.x, kv.y), h2u(kv.z, kv.w) };
            uint2 vh = { h2u(vv.x, vv.y), h2u(vv.z, vv.w) };
            *(uint2*)&g_kh[dst] = kh;
            *(uint2*)&g_vh[dst] = vh;
        }
        return;
    }

    extern __shared__ __half sh[];
    __half* bufA[2] = { sh,      sh + 2 * HA };
    __half* bufB[2] = { sh + HA, sh + 3 * HA };

    const __half* A    = (mode < 3) ? g_xh : g_ah;
    const __half* W    = (mode == 0) ? g_wqh : (mode == 1) ? g_wkh
                        : (mode == 2) ? g_wvh : g_woh;
    const float* bias  = (mode == 0) ? bq : (mode == 1) ? bk
                        : (mode == 2) ? bv : bo;

    const int tid  = threadIdx.x;
    const int lane = tid & 31, wid = tid >> 5;
    const int wm = wid >> 1, wn = wid & 1;
    const int g = lane >> 2, t = lane & 3;
    const int brow = blockIdx.y * 128, bcol = blockIdx.x * 128;

    const unsigned lmo = (((lane & 15) * GAP) + (lane >> 4) * 8) * 2;  // bytes

    float acc[2][8][4];
#pragma unroll
    for (int mi = 0; mi < 2; mi++)
#pragma unroll
        for (int nj = 0; nj < 8; nj++)
#pragma unroll
            for (int q = 0; q < 4; q++) acc[mi][nj][q] = 0.f;

    // prologue: buffer 0 (k0 = 0)
#pragma unroll
    for (int l = 0; l < 4; l++) {
        int idx = tid + l * 256;
        int r = idx >> 3, c = (idx & 7) * 8;
        CP16(s2u(&bufA[0][r * GAP + c]), &A[(size_t)(brow + r) * E_ + c]);
        CP16(s2u(&bufB[0][r * GAP + c]), &W[(size_t)(bcol + r) * E_ + c]);
    }
    CP_COMMIT();

    const int KT = E_ / 64;  // 32
    for (int kt = 0; kt < KT; kt++) {
        const int cur = kt & 1;
        CP_WAIT0();
        __syncthreads();
        if (kt + 1 < KT) {
            const int k0 = (kt + 1) * 64;
#pragma unroll
            for (int l = 0; l < 4; l++) {
                int idx = tid + l * 256;
                int r = idx >> 3, c = (idx & 7) * 8;
                CP16(s2u(&bufA[cur ^ 1][r * GAP + c]), &A[(size_t)(brow + r) * E_ + k0 + c]);
                CP16(s2u(&bufB[cur ^ 1][r * GAP + c]), &W[(size_t)(bcol + r) * E_ + k0 + c]);
            }
            CP_COMMIT();
        }

        const unsigned aBase = s2u(bufA[cur]) + (unsigned)(wm * 32 * GAP * 2) + lmo;
        const unsigned bBase = s2u(bufB[cur]) + (unsigned)(wn * 64 * GAP * 2) + lmo;

#pragma unroll
        for (int ks = 0; ks < 4; ks++) {
            const unsigned koff = ks * 32;    // 16 halfs = 32 bytes
            unsigned a[2][4];
            ldm_x4(a[0], aBase + koff);
            ldm_x4(a[1], aBase + 16 * GAP * 2 + koff);
            unsigned bfr[2][4];
            ldm_x4(bfr[0], bBase + koff);
#pragma unroll
            for (int njp = 0; njp < 4; njp++) {
                const int c2 = njp & 1;
                if (njp < 3)
                    ldm_x4(bfr[c2 ^ 1], bBase + (njp + 1) * 16 * GAP * 2 + koff);
                mma_f16(acc[0][2 * njp],     a[0][0], a[0][1], a[0][2], a[0][3], bfr[c2][0], bfr[c2][2]);
                mma_f16(acc[0][2 * njp + 1], a[0][0], a[0][1], a[0][2], a[0][3], bfr[c2][1], bfr[c2][3]);
                mma_f16(acc[1][2 * njp],     a[1][0], a[1][1], a[1][2], a[1][3], bfr[c2][0], bfr[c2][2]);
                mma_f16(acc[1][2 * njp + 1], a[1][0], a[1][1], a[1][2], a[1][3], bfr[c2][1], bfr[c2][3]);
            }
        }
    }
    __syncthreads();

    // epilogue
#pragma unroll
    for (int mi = 0; mi < 2; mi++) {
#pragma unroll
        for (int nj = 0; nj < 8; nj++) {
            int row = brow + wm * 32 + mi * 16 + g;
            int col = bcol + wn * 64 + nj * 8 + 2 * t;
            float b0 = bias[col], b1 = bias[col + 1];
            float v00 = acc[mi][nj][0] + b0, v01 = acc[mi][nj][1] + b1;
            float v10 = acc[mi][nj][2] + b0, v11 = acc[mi][nj][3] + b1;
            if (mode == 0) {
                *(unsigned*)&g_qh[(size_t)row * E_ + col] =
                    h2u(v00 * QSCALE, v01 * QSCALE);
                *(unsigned*)&g_qh[(size_t)(row + 8) * E_ + col] =
                    h2u(v10 * QSCALE, v11 * QSCALE);
            } else if (mode == 4) {
                float2 f0 = { v00, v01 }, f1 = { v10, v11 };
                *(float2*)&outp[(size_t)row * E_ + col]       = f0;
                *(float2*)&outp[(size_t)(row + 8) * E_ + col] = f1;
            } else {
                float* dst   = (mode == 1) ? kc  : vc;
                __half* dstH = (mode == 1) ? g_kh : g_vh;
                int b_i = row >> 10, t_i = row & 1023;
                int h_i = col >> 7,  d_i = col & 127;
                size_t base = ((size_t)(b_i * H_ + h_i) * S_ + TP_ + t_i) * D_ + d_i;
                float2 f0 = { v00, v01 }, f1 = { v10, v11 };
                *(float2*)&dst[base]             = f0;
                *(float2*)&dst[base + 8ull * D_] = f1;
                *(unsigned*)&dstH[base]             = h2u(v00, v01);
                *(unsigned*)&dstH[base + 8ull * D_] = h2u(v10, v11);
            }
        }
    }
}

// ---------------------------------------------------------------------------
// fp16 tensor-core flash attention.
// P stays in registers (QK c-frag layout == PV a-frag layout). No sP buffer.
// Register-pipelined K/V ldmatrix. Rescale skipped when running max unchanged.
// ---------------------------------------------------------------------------
#define QPH 136
#define KPH 136
#define VPH 136
#define ATTN_SMEM ((128*QPH + 2*64*KPH + 64*VPH) * 2)   // 87040 bytes

__global__ __launch_bounds__(256, 2) void attn_h(void)
{
    extern __shared__ __half sm[];
    __half* sQ = sm;                         // 128 x 136
    __half* sK = sQ + 128 * QPH;             // 2 x 64 x 136
    __half* sV = sK + 2 * 64 * KPH;          // 64 x 136

    const int qt = blockIdx.x, h = blockIdx.y, b = blockIdx.z;
    const int tid = threadIdx.x, lane = tid & 31, w = tid >> 5;

    const __half* kb = g_kh + (size_t)(b * H_ + h) * S_ * D_;
    const __half* vb = g_vh + (size_t)(b * H_ + h) * S_ * D_;

    // prologue: prefetch K chunk 0
#pragma unroll
    for (int l = 0; l < 4; l++) {
        int idx = tid + l * 256;
        int r = idx >> 4, c = (idx & 15) * 8;
        CP16(s2u(&sK[r * KPH + c]), &kb[(size_t)r * D_ + c]);
    }
    CP_COMMIT();

    // stage Q tile (fp16, already scaled)
#pragma unroll
    for (int l = 0; l < 8; l++) {
        int idx = tid + l * 256;
        int r = idx >> 4, c = (idx & 15) * 8;
        uint4 qv = *(const uint4*)&g_qh[(size_t)(b * T_ + qt * 128 + r) * E_ + h * D_ + c];
        *(uint4*)&sQ[r * QPH + c] = qv;
    }

    float m0 = -1e30f, m1 = -1e30f, l0 = 0.f, l1 = 0.f;
    float acc_o[16][4];
#pragma unroll
    for (int nj = 0; nj < 16; nj++)
#pragma unroll
        for (int q = 0; q < 4; q++) acc_o[nj][q] = 0.f;

    const unsigned lmoQ = (((lane & 15) * QPH) + (lane >> 4) * 8) * 2;
    const unsigned lmoK = (((lane & 15) * KPH) + (lane >> 4) * 8) * 2;
    const unsigned aQBase = s2u(sQ) + (unsigned)(w * 16 * QPH * 2) + lmoQ;

    for (int ci = 0; ci < S_ / 64; ci++) {
        const int cur = ci & 1;
        const unsigned bKBase = s2u(sK + cur * 64 * KPH) + lmoK;

        CP_WAIT0();
        __syncthreads();

        // prefetch V_ci, then K_{ci+1}
        {
            const size_t vbase = (size_t)(ci * 64) * D_;
#pragma unroll
            for (int l = 0; l < 4; l++) {
                int idx = tid + l * 256;
                int r = idx >> 4, c = (idx & 15) * 8;
                CP16(s2u(&sV[r * VPH + c]), &vb[vbase + (size_t)r * D_ + c]);
            }
            CP_COMMIT();
        }
        if (ci + 1 < S_ / 64) {
            const size_t kbase = (size_t)((ci + 1) * 64) * D_;
            __half* nK = sK + (cur ^ 1) * 64 * KPH;
#pragma unroll
            for (int l = 0; l < 4; l++) {
                int idx = tid + l * 256;
                int r = idx >> 4, c = (idx & 15) * 8;
                CP16(s2u(&nK[r * KPH + c]), &kb[kbase + (size_t)r * D_ + c]);
            }
            CP_COMMIT();
        }

        // S = Q K^T   (warp: 16 q-rows x 64 keys, 8 k-steps)
        float accs[8][4];
#pragma unroll
        for (int nj = 0; nj < 8; nj++)
#pragma unroll
            for (int q = 0; q < 4; q++) accs[nj][q] = 0.f;

#pragma unroll
        for (int ks = 0; ks < 8; ks++) {
            const unsigned koff = ks * 32;
            unsigned a[4];
            ldm_x4(a, aQBase + koff);
            unsigned bfr[2][4];
            ldm_x4(bfr[0], bKBase + koff);
#pragma unroll
            for (int njp = 0; njp < 4; njp++) {
                const int c2 = njp & 1;
                if (njp < 3)
                    ldm_x4(bfr[c2 ^ 1], bKBase + (njp + 1) * 16 * KPH * 2 + koff);
                mma_f16(accs[2 * njp],     a[0], a[1], a[2], a[3], bfr[c2][0], bfr[c2][2]);
                mma_f16(accs[2 * njp + 1], a[0], a[1], a[2], a[3], bfr[c2][1], bfr[c2][3]);
            }
        }

        // online softmax
        float rm0 = -1e30f, rm1 = -1e30f;
#pragma unroll
        for (int nj = 0; nj < 8; nj++) {
            rm0 = fmaxf(rm0, fmaxf(accs[nj][0], accs[nj][1]));
            rm1 = fmaxf(rm1, fmaxf(accs[nj][2], accs[nj][3]));
        }
        rm0 = fmaxf(rm0, __shfl_xor_sync(0xffffffffu, rm0, 1));
        rm0 = fmaxf(rm0, __shfl_xor_sync(0xffffffffu, rm0, 2));
        rm1 = fmaxf(rm1, __shfl_xor_sync(0xffffffffu, rm1, 1));
        rm1 = fmaxf(rm1, __shfl_xor_sync(0xffffffffu, rm1, 2));

        float nm0 = fmaxf(m0, rm0), nm1 = fmaxf(m1, rm1);
        float al0 = __expf(m0 - nm0), al1 = __expf(m1 - nm1);
        m0 = nm0; m1 = nm1;

        // P in registers: pA[nj] = (p(g,2t), p(g,2t+1)), pB[nj] = rows g+8.
        unsigned pA[8], pB[8];
        float sum0 = 0.f, sum1 = 0.f;
#pragma unroll
        for (int nj = 0; nj < 8; nj++) {
            float p0 = __expf(accs[nj][0] - nm0);
            float p1 = __expf(accs[nj][1] - nm0);
            float p2 = __expf(accs[nj][2] - nm1);
            float p3 = __expf(accs[nj][3] - nm1);
            sum0 += p0 + p1;
            sum1 += p2 + p3;
            pA[nj] = h2u(p0, p1);
            pB[nj] = h2u(p2, p3);
        }
        sum0 += __shfl_xor_sync(0xffffffffu, sum0, 1);
        sum0 += __shfl_xor_sync(0xffffffffu, sum0, 2);
        sum1 += __shfl_xor_sync(0xffffffffu, sum1, 1);
        sum1 += __shfl_xor_sync(0xffffffffu, sum1, 2);
        l0 = l0 * al0 + sum0;
        l1 = l1 * al1 + sum1;

        // rescale only if any lane's max changed (exact: al==1.0f otherwise)
        if (!__all_sync(0xffffffffu, (al0 == 1.f) && (al1 == 1.f))) {
#pragma unroll
            for (int nj = 0; nj < 16; nj++) {
                acc_o[nj][0] *= al0; acc_o[nj][1] *= al0;
                acc_o[nj][2] *= al1; acc_o[nj][3] *= al1;
            }
        }

        if (ci + 1 < S_ / 64) { CP_WAIT1(); } else { CP_WAIT0(); }
        __syncthreads();

        // O += P V   (P a-frags from registers; V b-frags via ldmatrix.trans)
#pragma unroll
        for (int ks = 0; ks < 4; ks++) {
            const unsigned a0 = pA[2 * ks],     a1 = pB[2 * ks];
            const unsigned a2 = pA[2 * ks + 1], a3 = pB[2 * ks + 1];
            int key = ks * 16 + (lane & 15);
            unsigned bb[2][4];
            ldm_x4_trans(bb[0], s2u(&sV[key * VPH + (lane >> 4) * 8]));
#pragma unroll
            for (int nj2 = 0; nj2 < 8; nj2++) {
                const int c2 = nj2 & 1;
                if (nj2 < 7) {
                    int dd = (nj2 + 1) * 16 + (lane >> 4) * 8;
                    ldm_x4_trans(bb[c2 ^ 1], s2u(&sV[key * VPH + dd]));
                }
                mma_f16(acc_o[nj2 * 2],     a0, a1, a2, a3, bb[c2][0], bb[c2][1]);
                mma_f16(acc_o[nj2 * 2 + 1], a0, a1, a2, a3, bb[c2][2], bb[c2][3]);
            }
        }
    }

    // epilogue: normalize, write fp16 to g_ah
    const int g = lane >> 2, t = lane & 3;
    float inv0 = 1.f / l0, inv1 = 1.f / l1;
    int row = b * T_ + qt * 128 + w * 16 + g;
#pragma unroll
    for (int nj = 0; nj < 16; nj++) {
        int col = h * D_ + nj * 8 + 2 * t;
        *(unsigned*)&g_ah[(size_t)row * E_ + col] =
            h2u(acc_o[nj][0] * inv0, acc_o[nj][1] * inv0);
        *(unsigned*)&g_ah[(size_t)(row + 8) * E_ + col] =
            h2u(acc_o[nj][2] * inv1, acc_o[nj][3] * inv1);
    }
}

// ---------------------------------------------------------------------------
extern "C" void kernel_launch(void* const* d_in, const int* in_sizes, int n_in,
                              void* d_out, int out_size)
{
    const float* x      = (const float*)d_in[0];
    const float* past_k = (const float*)d_in[1];
    const float* past_v = (const float*)d_in[2];
    const float* Wq     = (const float*)d_in[3];
    const float* bq     = (const float*)d_in[4];
    const float* Wk     = (const float*)d_in[5];
    const float* bk     = (const float*)d_in[6];
    const float* Wv     = (const float*)d_in[7];
    const float* bv     = (const float*)d_in[8];
    const float* Wo     = (const float*)d_in[9];
    const float* bo     = (const float*)d_in[10];

    float* out = (float*)d_out;                       // [B,T,E]
    float* kc  = out + (size_t)NTOK * E_;             // [B,H,S,D]
    float* vc  = kc + (size_t)CACHE_ELEMS;            // [B,H,S,D]

    // fp32 -> fp16 conversions (single launch)
    to_half_all<<<dim3(512, 5), 256>>>(x, Wq, Wk, Wv, Wo);

    cudaFuncSetAttribute(gemm_h, cudaFuncAttributeMaxDynamicSharedMemorySize, GEMM_SMEM);
    cudaFuncSetAttribute(attn_h, cudaFuncAttributeMaxDynamicSharedMemorySize, ATTN_SMEM);

    // fused QKV projections (z=0..2) + past-KV copy (z=3) in one launch
    dim3 gq(E_ / 128, NTOK / 128, 4);
    gemm_h<<<gq, 256, GEMM_SMEM>>>(0, bq, bk, bv, bo, past_k, past_v,
                                   kc, vc, out);

    // attention
    attn_h<<<dim3(T_ / 128, H_, B_), 256, ATTN_SMEM>>>();

    // output projection (mode 4)
    dim3 go(E_ / 128, NTOK / 128, 1);
    gemm_h<<<go, 256, GEMM_SMEM>>>(4, bq, bk, bv, bo, past_k, past_v,
                                   kc, vc, out);
}

// round 11
// speedup vs baseline: 3.8175x; 1.0109x over previous
#include <cuda_runtime.h>
#include <cuda_fp16.h>
#include <math.h>
#include <stdint.h>

// Problem constants
#define E_   2048
#define H_   16
#define D_   128
#define B_   4
#define T_   1024
#define TP_  3072
#define S_   (TP_ + T_)      // 4096
#define NTOK (B_ * T_)       // 4096
#define CACHE_ELEMS (B_ * H_ * S_ * D_)   // 33.5M
#define QSCALE 0.08838834764831845f       // 1/sqrt(128)

// Scratch (device globals -- no allocations allowed)
__device__ __half g_xh[NTOK * E_];     // x in fp16
__device__ __half g_wqh[E_ * E_];
__device__ __half g_wkh[E_ * E_];
__device__ __half g_wvh[E_ * E_];
__device__ __half g_woh[E_ * E_];
__device__ __half g_qh[NTOK * E_];     // Q (scaled) fp16
__device__ __half g_ah[NTOK * E_];     // attention output fp16
__device__ __half g_kh[CACHE_ELEMS];   // K cache shadow fp16 [b,h,s,d]
__device__ __half g_vh[CACHE_ELEMS];   // V cache shadow fp16 [b,h,s,d]

// ---------------------------------------------------------------------------
// Helpers
// ---------------------------------------------------------------------------
__device__ __forceinline__ void mma_f16(float c[4],
    unsigned a0, unsigned a1, unsigned a2, unsigned a3,
    unsigned b0, unsigned b1)
{
    asm volatile(
        "mma.sync.aligned.m16n8k16.row.col.f32.f16.f16.f32 "
        "{%0,%1,%2,%3}, {%4,%5,%6,%7}, {%8,%9}, {%0,%1,%2,%3};"
        : "+f"(c[0]), "+f"(c[1]), "+f"(c[2]), "+f"(c[3])
        : "r"(a0), "r"(a1), "r"(a2), "r"(a3), "r"(b0), "r"(b1));
}

__device__ __forceinline__ unsigned s2u(const void* p) {
    return (unsigned)__cvta_generic_to_shared(p);
}

__device__ __forceinline__ unsigned h2u(float x, float y) {
    __half2 h = __floats2half2_rn(x, y);
    return *(unsigned*)&h;
}

#define CP16(dst_u32, src_ptr) \
    asm volatile("cp.async.cg.shared.global [%0], [%1], 16;" :: "r"(dst_u32), "l"(src_ptr))
#define CP_COMMIT() asm volatile("cp.async.commit_group;")
#define CP_WAIT0()  asm volatile("cp.async.wait_group 0;")
#define CP_WAIT1()  asm volatile("cp.async.wait_group 1;")

__device__ __forceinline__ void ldm_x4(unsigned r[4], unsigned addr) {
    asm volatile(
        "ldmatrix.sync.aligned.m8n8.x4.shared.b16 {%0,%1,%2,%3}, [%4];"
        : "=r"(r[0]), "=r"(r[1]), "=r"(r[2]), "=r"(r[3]) : "r"(addr));
}

__device__ __forceinline__ void ldm_x4_trans(unsigned r[4], unsigned addr) {
    asm volatile(
        "ldmatrix.sync.aligned.m8n8.x4.trans.shared.b16 {%0,%1,%2,%3}, [%4];"
        : "=r"(r[0]), "=r"(r[1]), "=r"(r[2]), "=r"(r[3]) : "r"(addr));
}

// ---------------------------------------------------------------------------
// Fused fp32 -> fp16 conversion (x + 4 weights in one launch)
// ---------------------------------------------------------------------------
__global__ void to_half_all(const float* __restrict__ x,
                            const float* __restrict__ wq,
                            const float* __restrict__ wk,
                            const float* __restrict__ wv,
                            const float* __restrict__ wo)
{
    const int z = blockIdx.y;
    const float* src = (z == 0) ? x : (z == 1) ? wq : (z == 2) ? wk
                      : (z == 3) ? wv : wo;
    __half* dst = (z == 0) ? g_xh : (z == 1) ? g_wqh : (z == 2) ? g_wkh
                 : (z == 3) ? g_wvh : g_woh;
    const int n4 = (z == 0) ? NTOK * E_ / 4 : E_ * E_ / 4;
    for (int i = blockIdx.x * blockDim.x + threadIdx.x; i < n4;
         i += gridDim.x * blockDim.x) {
        float4 v = ((const float4*)src)[i];
        uint2 u = { h2u(v.x, v.y), h2u(v.z, v.w) };
        ((uint2*)dst)[i] = u;
    }
}

// ---------------------------------------------------------------------------
// fp16 tensor-core GEMM + fused past-KV copy. 3-stage cp.async ring.
// mode = base_mode + blockIdx.z:
//   0=Q-proj, 1=K-proj, 2=V-proj, 3=past-KV copy, 4=O-proj.
// ---------------------------------------------------------------------------
#define GAP 72
#define HA  (128 * GAP)           // halfs per matrix per stage (9216)
#define GEMM_SMEM (6 * HA * 2)    // 110592 bytes (3 stages x A,B)

__global__ __launch_bounds__(256, 2) void gemm_h(
    int base_mode,
    const float* __restrict__ bq, const float* __restrict__ bk,
    const float* __restrict__ bv, const float* __restrict__ bo,
    const float* __restrict__ past_k, const float* __restrict__ past_v,
    float* __restrict__ kc, float* __restrict__ vc, float* __restrict__ outp)
{
    const int mode = base_mode + blockIdx.z;

    if (mode == 3) {
        // ---- past copy CTAs (grid-stride over float4s) ----
        const int total4 = B_ * H_ * TP_ * D_ / 4;
        const int nct = gridDim.x * gridDim.y;
        const int cta = blockIdx.y * gridDim.x + blockIdx.x;
        for (int idx = cta * 256 + threadIdx.x; idx < total4; idx += nct * 256) {
            int bh  = idx / (TP_ * D_ / 4);
            int off = (idx % (TP_ * D_ / 4)) * 4;
            size_t dst = (size_t)bh * S_ * D_ + off;
            float4 kv = *(const float4*)&past_k[(size_t)idx * 4];
            float4 vv = *(const float4*)&past_v[(size_t)idx * 4];
            *(float4*)&kc[dst] = kv;
            *(float4*)&vc[dst] = vv;
            uint2 kh = { h2u(kv.x, kv.y), h2u(kv.z, kv.w) };
            uint2 vh = { h2u(vv.x, vv.y), h2u(vv.z, vv.w) };
            *(uint2*)&g_kh[dst] = kh;
            *(uint2*)&g_vh[dst] = vh;
        }
        return;
    }

    extern __shared__ __half sh[];
    // stage s: A at sh + s*2*HA, B at sh + s*2*HA + HA

    const __half* A    = (mode < 3) ? g_xh : g_ah;
    const __half* W    = (mode == 0) ? g_wqh : (mode == 1) ? g_wkh
                        : (mode == 2) ? g_wvh : g_woh;
    const float* bias  = (mode == 0) ? bq : (mode == 1) ? bk
                        : (mode == 2) ? bv : bo;

    const int tid  = threadIdx.x;
    const int lane = tid & 31, wid = tid >> 5;
    const int wm = wid >> 1, wn = wid & 1;
    const int g = lane >> 2, t = lane & 3;
    const int brow = blockIdx.y * 128, bcol = blockIdx.x * 128;

    const unsigned lmo = (((lane & 15) * GAP) + (lane >> 4) * 8) * 2;  // bytes

    float acc[2][8][4];
#pragma unroll
    for (int mi = 0; mi < 2; mi++)
#pragma unroll
        for (int nj = 0; nj < 8; nj++)
#pragma unroll
            for (int q = 0; q < 4; q++) acc[mi][nj][q] = 0.f;

    // prologue: stages 0 and 1 (tiles 0, 1)
#pragma unroll
    for (int s = 0; s < 2; s++) {
        __half* bA = sh + s * 2 * HA;
        __half* bB = bA + HA;
        const int k0 = s * 64;
#pragma unroll
        for (int l = 0; l < 4; l++) {
            int idx = tid + l * 256;
            int r = idx >> 3, c = (idx & 7) * 8;
            CP16(s2u(&bA[r * GAP + c]), &A[(size_t)(brow + r) * E_ + k0 + c]);
            CP16(s2u(&bB[r * GAP + c]), &W[(size_t)(bcol + r) * E_ + k0 + c]);
        }
        CP_COMMIT();
    }

    const int KT = E_ / 64;  // 32
    for (int kt = 0; kt < KT; kt++) {
        if (kt < KT - 1) { CP_WAIT1(); } else { CP_WAIT0(); }
        __syncthreads();

        if (kt + 2 < KT) {
            const int s = (kt + 2) % 3;
            __half* bA = sh + s * 2 * HA;
            __half* bB = bA + HA;
            const int k0 = (kt + 2) * 64;
#pragma unroll
            for (int l = 0; l < 4; l++) {
                int idx = tid + l * 256;
                int r = idx >> 3, c = (idx & 7) * 8;
                CP16(s2u(&bA[r * GAP + c]), &A[(size_t)(brow + r) * E_ + k0 + c]);
                CP16(s2u(&bB[r * GAP + c]), &W[(size_t)(bcol + r) * E_ + k0 + c]);
            }
            CP_COMMIT();
        }

        const int cs = kt % 3;
        const unsigned aBase = s2u(sh + cs * 2 * HA) + (unsigned)(wm * 32 * GAP * 2) + lmo;
        const unsigned bBase = s2u(sh + cs * 2 * HA + HA) + (unsigned)(wn * 64 * GAP * 2) + lmo;

#pragma unroll
        for (int ks = 0; ks < 4; ks++) {
            const unsigned koff = ks * 32;    // 16 halfs = 32 bytes
            unsigned a[2][4];
            ldm_x4(a[0], aBase + koff);
            ldm_x4(a[1], aBase + 16 * GAP * 2 + koff);
            unsigned bfr[2][4];
            ldm_x4(bfr[0], bBase + koff);
#pragma unroll
            for (int njp = 0; njp < 4; njp++) {
                const int c2 = njp & 1;
                if (njp < 3)
                    ldm_x4(bfr[c2 ^ 1], bBase + (njp + 1) * 16 * GAP * 2 + koff);
                mma_f16(acc[0][2 * njp],     a[0][0], a[0][1], a[0][2], a[0][3], bfr[c2][0], bfr[c2][2]);
                mma_f16(acc[0][2 * njp + 1], a[0][0], a[0][1], a[0][2], a[0][3], bfr[c2][1], bfr[c2][3]);
                mma_f16(acc[1][2 * njp],     a[1][0], a[1][1], a[1][2], a[1][3], bfr[c2][0], bfr[c2][2]);
                mma_f16(acc[1][2 * njp + 1], a[1][0], a[1][1], a[1][2], a[1][3], bfr[c2][1], bfr[c2][3]);
            }
        }
    }
    __syncthreads();

    // epilogue
#pragma unroll
    for (int mi = 0; mi < 2; mi++) {
#pragma unroll
        for (int nj = 0; nj < 8; nj++) {
            int row = brow + wm * 32 + mi * 16 + g;
            int col = bcol + wn * 64 + nj * 8 + 2 * t;
            float b0 = bias[col], b1 = bias[col + 1];
            float v00 = acc[mi][nj][0] + b0, v01 = acc[mi][nj][1] + b1;
            float v10 = acc[mi][nj][2] + b0, v11 = acc[mi][nj][3] + b1;
            if (mode == 0) {
                *(unsigned*)&g_qh[(size_t)row * E_ + col] =
                    h2u(v00 * QSCALE, v01 * QSCALE);
                *(unsigned*)&g_qh[(size_t)(row + 8) * E_ + col] =
                    h2u(v10 * QSCALE, v11 * QSCALE);
            } else if (mode == 4) {
                float2 f0 = { v00, v01 }, f1 = { v10, v11 };
                *(float2*)&outp[(size_t)row * E_ + col]       = f0;
                *(float2*)&outp[(size_t)(row + 8) * E_ + col] = f1;
            } else {
                float* dst   = (mode == 1) ? kc  : vc;
                __half* dstH = (mode == 1) ? g_kh : g_vh;
                int b_i = row >> 10, t_i = row & 1023;
                int h_i = col >> 7,  d_i = col & 127;
                size_t base = ((size_t)(b_i * H_ + h_i) * S_ + TP_ + t_i) * D_ + d_i;
                float2 f0 = { v00, v01 }, f1 = { v10, v11 };
                *(float2*)&dst[base]             = f0;
                *(float2*)&dst[base + 8ull * D_] = f1;
                *(unsigned*)&dstH[base]             = h2u(v00, v01);
                *(unsigned*)&dstH[base + 8ull * D_] = h2u(v10, v11);
            }
        }
    }
}

// ---------------------------------------------------------------------------
// fp16 tensor-core flash attention.
// K and V both double-buffered, loaded together one chunk ahead in a single
// cp.async group -> ONE __syncthreads per chunk. P stays in registers.
// ---------------------------------------------------------------------------
#define QPH 136
#define KPH 136
#define VPH 136
#define ATTN_SMEM ((128*QPH + 2*64*KPH + 2*64*VPH) * 2)   // 104448 bytes

__global__ __launch_bounds__(256, 2) void attn_h(void)
{
    extern __shared__ __half sm[];
    __half* sQ = sm;                         // 128 x 136
    __half* sK = sQ + 128 * QPH;             // 2 x 64 x 136
    __half* sV = sK + 2 * 64 * KPH;          // 2 x 64 x 136

    const int qt = blockIdx.x, h = blockIdx.y, b = blockIdx.z;
    const int tid = threadIdx.x, lane = tid & 31, w = tid >> 5;

    const __half* kb = g_kh + (size_t)(b * H_ + h) * S_ * D_;
    const __half* vb = g_vh + (size_t)(b * H_ + h) * S_ * D_;

    // prologue: prefetch K0 + V0 in one group
#pragma unroll
    for (int l = 0; l < 4; l++) {
        int idx = tid + l * 256;
        int r = idx >> 4, c = (idx & 15) * 8;
        CP16(s2u(&sK[r * KPH + c]), &kb[(size_t)r * D_ + c]);
        CP16(s2u(&sV[r * VPH + c]), &vb[(size_t)r * D_ + c]);
    }
    CP_COMMIT();

    // stage Q tile (fp16, already scaled)
#pragma unroll
    for (int l = 0; l < 8; l++) {
        int idx = tid + l * 256;
        int r = idx >> 4, c = (idx & 15) * 8;
        uint4 qv = *(const uint4*)&g_qh[(size_t)(b * T_ + qt * 128 + r) * E_ + h * D_ + c];
        *(uint4*)&sQ[r * QPH + c] = qv;
    }

    float m0 = -1e30f, m1 = -1e30f, l0 = 0.f, l1 = 0.f;
    float acc_o[16][4];
#pragma unroll
    for (int nj = 0; nj < 16; nj++)
#pragma unroll
        for (int q = 0; q < 4; q++) acc_o[nj][q] = 0.f;

    const unsigned lmoQ = (((lane & 15) * QPH) + (lane >> 4) * 8) * 2;
    const unsigned lmoK = (((lane & 15) * KPH) + (lane >> 4) * 8) * 2;
    const unsigned aQBase = s2u(sQ) + (unsigned)(w * 16 * QPH * 2) + lmoQ;

    for (int ci = 0; ci < S_ / 64; ci++) {
        const int cur = ci & 1;
        const unsigned bKBase = s2u(sK + cur * 64 * KPH) + lmoK;
        __half* cV = sV + cur * 64 * VPH;

        CP_WAIT0();
        __syncthreads();   // chunk ci resident; all warps done with ci-1 buffers

        // prefetch K_{ci+1} + V_{ci+1} into the freed buffers
        if (ci + 1 < S_ / 64) {
            const size_t nbase = (size_t)((ci + 1) * 64) * D_;
            __half* nK = sK + (cur ^ 1) * 64 * KPH;
            __half* nV = sV + (cur ^ 1) * 64 * VPH;
#pragma unroll
            for (int l = 0; l < 4; l++) {
                int idx = tid + l * 256;
                int r = idx >> 4, c = (idx & 15) * 8;
                CP16(s2u(&nK[r * KPH + c]), &kb[nbase + (size_t)r * D_ + c]);
                CP16(s2u(&nV[r * VPH + c]), &vb[nbase + (size_t)r * D_ + c]);
            }
            CP_COMMIT();
        }

        // S = Q K^T   (warp: 16 q-rows x 64 keys, 8 k-steps)
        float accs[8][4];
#pragma unroll
        for (int nj = 0; nj < 8; nj++)
#pragma unroll
            for (int q = 0; q < 4; q++) accs[nj][q] = 0.f;

#pragma unroll
        for (int ks = 0; ks < 8; ks++) {
            const unsigned koff = ks * 32;
            unsigned a[4];
            ldm_x4(a, aQBase + koff);
            unsigned bfr[2][4];
            ldm_x4(bfr[0], bKBase + koff);
#pragma unroll
            for (int njp = 0; njp < 4; njp++) {
                const int c2 = njp & 1;
                if (njp < 3)
                    ldm_x4(bfr[c2 ^ 1], bKBase + (njp + 1) * 16 * KPH * 2 + koff);
                mma_f16(accs[2 * njp],     a[0], a[1], a[2], a[3], bfr[c2][0], bfr[c2][2]);
                mma_f16(accs[2 * njp + 1], a[0], a[1], a[2], a[3], bfr[c2][1], bfr[c2][3]);
            }
        }

        // online softmax
        float rm0 = -1e30f, rm1 = -1e30f;
#pragma unroll
        for (int nj = 0; nj < 8; nj++) {
            rm0 = fmaxf(rm0, fmaxf(accs[nj][0], accs[nj][1]));
            rm1 = fmaxf(rm1, fmaxf(accs[nj][2], accs[nj][3]));
        }
        rm0 = fmaxf(rm0, __shfl_xor_sync(0xffffffffu, rm0, 1));
        rm0 = fmaxf(rm0, __shfl_xor_sync(0xffffffffu, rm0, 2));
        rm1 = fmaxf(rm1, __shfl_xor_sync(0xffffffffu, rm1, 1));
        rm1 = fmaxf(rm1, __shfl_xor_sync(0xffffffffu, rm1, 2));

        float nm0 = fmaxf(m0, rm0), nm1 = fmaxf(m1, rm1);
        float al0 = __expf(m0 - nm0), al1 = __expf(m1 - nm1);
        m0 = nm0; m1 = nm1;

        unsigned pA[8], pB[8];
        float sum0 = 0.f, sum1 = 0.f;
#pragma unroll
        for (int nj = 0; nj < 8; nj++) {
            float p0 = __expf(accs[nj][0] - nm0);
            float p1 = __expf(accs[nj][1] - nm0);
            float p2 = __expf(accs[nj][2] - nm1);
            float p3 = __expf(accs[nj][3] - nm1);
            sum0 += p0 + p1;
            sum1 += p2 + p3;
            pA[nj] = h2u(p0, p1);
            pB[nj] = h2u(p2, p3);
        }
        sum0 += __shfl_xor_sync(0xffffffffu, sum0, 1);
        sum0 += __shfl_xor_sync(0xffffffffu, sum0, 2);
        sum1 += __shfl_xor_sync(0xffffffffu, sum1, 1);
        sum1 += __shfl_xor_sync(0xffffffffu, sum1, 2);
        l0 = l0 * al0 + sum0;
        l1 = l1 * al1 + sum1;

        if (!__all_sync(0xffffffffu, (al0 == 1.f) && (al1 == 1.f))) {
#pragma unroll
            for (int nj = 0; nj < 16; nj++) {
                acc_o[nj][0] *= al0; acc_o[nj][1] *= al0;
                acc_o[nj][2] *= al1; acc_o[nj][3] *= al1;
            }
        }

        // O += P V   (V already resident; no extra wait/sync)
#pragma unroll
        for (int ks = 0; ks < 4; ks++) {
            const unsigned a0 = pA[2 * ks],     a1 = pB[2 * ks];
            const unsigned a2 = pA[2 * ks + 1], a3 = pB[2 * ks + 1];
            int key = ks * 16 + (lane & 15);
            unsigned bb[2][4];
            ldm_x4_trans(bb[0], s2u(&cV[key * VPH + (lane >> 4) * 8]));
#pragma unroll
            for (int nj2 = 0; nj2 < 8; nj2++) {
                const int c2 = nj2 & 1;
                if (nj2 < 7) {
                    int dd = (nj2 + 1) * 16 + (lane >> 4) * 8;
                    ldm_x4_trans(bb[c2 ^ 1], s2u(&cV[key * VPH + dd]));
                }
                mma_f16(acc_o[nj2 * 2],     a0, a1, a2, a3, bb[c2][0], bb[c2][1]);
                mma_f16(acc_o[nj2 * 2 + 1], a0, a1, a2, a3, bb[c2][2], bb[c2][3]);
            }
        }
    }

    // epilogue: normalize, write fp16 to g_ah
    const int g = lane >> 2, t = lane & 3;
    float inv0 = 1.f / l0, inv1 = 1.f / l1;
    int row = b * T_ + qt * 128 + w * 16 + g;
#pragma unroll
    for (int nj = 0; nj < 16; nj++) {
        int col = h * D_ + nj * 8 + 2 * t;
        *(unsigned*)&g_ah[(size_t)row * E_ + col] =
            h2u(acc_o[nj][0] * inv0, acc_o[nj][1] * inv0);
        *(unsigned*)&g_ah[(size_t)(row + 8) * E_ + col] =
            h2u(acc_o[nj][2] * inv1, acc_o[nj][3] * inv1);
    }
}

// ---------------------------------------------------------------------------
extern "C" void kernel_launch(void* const* d_in, const int* in_sizes, int n_in,
                              void* d_out, int out_size)
{
    const float* x      = (const float*)d_in[0];
    const float* past_k = (const float*)d_in[1];
    const float* past_v = (const float*)d_in[2];
    const float* Wq     = (const float*)d_in[3];
    const float* bq     = (const float*)d_in[4];
    const float* Wk     = (const float*)d_in[5];
    const float* bk     = (const float*)d_in[6];
    const float* Wv     = (const float*)d_in[7];
    const float* bv     = (const float*)d_in[8];
    const float* Wo     = (const float*)d_in[9];
    const float* bo     = (const float*)d_in[10];

    float* out = (float*)d_out;                       // [B,T,E]
    float* kc  = out + (size_t)NTOK * E_;             // [B,H,S,D]
    float* vc  = kc + (size_t)CACHE_ELEMS;            // [B,H,S,D]

    // fp32 -> fp16 conversions (single launch)
    to_half_all<<<dim3(512, 5), 256>>>(x, Wq, Wk, Wv, Wo);

    cudaFuncSetAttribute(gemm_h, cudaFuncAttributeMaxDynamicSharedMemorySize, GEMM_SMEM);
    cudaFuncSetAttribute(attn_h, cudaFuncAttributeMaxDynamicSharedMemorySize, ATTN_SMEM);

    // fused QKV projections (z=0..2) + past-KV copy (z=3) in one launch
    dim3 gq(E_ / 128, NTOK / 128, 4);
    gemm_h<<<gq, 256, GEMM_SMEM>>>(0, bq, bk, bv, bo, past_k, past_v,
                                   kc, vc, out);

    // attention
    attn_h<<<dim3(T_ / 128, H_, B_), 256, ATTN_SMEM>>>();

    // output projection (mode 4)
    dim3 go(E_ / 128, NTOK / 128, 1);
    gemm_h<<<go, 256, GEMM_SMEM>>>(4, bq, bk, bv, bo, past_k, past_v,
                                   kc, vc, out);
}